// round 1
// baseline (speedup 1.0000x reference)
#include <cuda_runtime.h>
#include <math.h>

#define B_   16384
#define F_   32
#define V_   50000
#define DE   16
#define DIN  512
#define NE   6
#define H1_  512
#define H2_  256
#define T1_  128
#define T2_  64

// ---------------- scratch (device globals; no runtime alloc) ----------------
__device__ float g_X [(size_t)B_*DIN];        // embed_x            32 MB
__device__ float g_H [(size_t)NE*B_*H1_];     // expert hidden     192 MB
__device__ float g_O [(size_t)NE*B_*H2_];     // expert outputs     96 MB
__device__ float g_X2[(size_t)3 *B_*H2_];     // level-1 combined   48 MB
__device__ float g_X3[(size_t)2 *B_*H2_];     // level-2 combined   32 MB
__device__ float g_T [(size_t)2 *B_*T1_];     // tower hidden       16 MB

// ---------------- embedding gather ----------------
__global__ void gather_kernel(const int* __restrict__ ids,
                              const float* __restrict__ emb) {
    int idx = blockIdx.x * blockDim.x + threadIdx.x;   // idx = b*F + f
    if (idx >= B_ * F_) return;
    int f  = idx & (F_ - 1);
    int id = ids[idx];
    const float4* src = reinterpret_cast<const float4*>(emb + ((size_t)f * V_ + id) * DE);
    float4* dst = reinterpret_cast<float4*>(g_X + (size_t)idx * DE); // b*512 + f*16
    dst[0] = src[0]; dst[1] = src[1]; dst[2] = src[2]; dst[3] = src[3];
}

// ---------------- generic grouped GEMM: C = act(A_e @ W_e + b_e) ----------------
// A: [M,K] row-major, selected per expert via a_sel (0: shared, 1: e/2, 2: e)
// W: [E,K,N], bias: [E,N]
// C element (e,row,col) at  C + e*cExpStride + row*ldc + col
// act: 0 = relu, 1 = sigmoid
#define BM 128
#define BN 64
#define BK 16

__global__ void __launch_bounds__(256)
gemm_kernel(const float* __restrict__ A, const float* __restrict__ W,
            const float* __restrict__ bias, float* __restrict__ C,
            int M, int N, int K, int a_sel,
            size_t cExpStride, int ldc, int act)
{
    __shared__ float As[BK][BM];
    __shared__ float Ws[BK][BN];

    int e    = blockIdx.z;
    int aidx = (a_sel == 0) ? 0 : ((a_sel == 1) ? (e >> 1) : e);
    const float* Ae = A    + (size_t)aidx * M * K;
    const float* We = W    + (size_t)e    * K * N;
    const float* be = bias + (size_t)e    * N;

    int m0  = blockIdx.y * BM;
    int n0  = blockIdx.x * BN;
    int tid = threadIdx.x;
    int tx  = tid & 15;          // N direction: 16 * 4 = 64
    int ty  = tid >> 4;          // M direction: 16 * 8 = 128

    float acc[8][4];
    #pragma unroll
    for (int i = 0; i < 8; i++)
        #pragma unroll
        for (int j = 0; j < 4; j++) acc[i][j] = 0.f;

    for (int k0 = 0; k0 < K; k0 += BK) {
        // A tile: 128x16 floats = 512 float4 loads, 2 per thread
        #pragma unroll
        for (int t = 0; t < 2; t++) {
            int id = tid + t * 256;
            int r  = id >> 2;
            int c4 = id & 3;
            float4 v = *reinterpret_cast<const float4*>(Ae + (size_t)(m0 + r) * K + k0 + c4 * 4);
            As[c4*4+0][r] = v.x; As[c4*4+1][r] = v.y;
            As[c4*4+2][r] = v.z; As[c4*4+3][r] = v.w;
        }
        // W tile: 16x64 floats = 256 float4 loads, 1 per thread
        {
            int kk = tid >> 4;
            int n4 = tid & 15;
            float4 v = *reinterpret_cast<const float4*>(We + (size_t)(k0 + kk) * N + n0 + n4 * 4);
            *reinterpret_cast<float4*>(&Ws[kk][n4 * 4]) = v;
        }
        __syncthreads();

        #pragma unroll
        for (int kk = 0; kk < BK; kk++) {
            float a[8], w[4];
            #pragma unroll
            for (int i = 0; i < 8; i++) a[i] = As[kk][ty * 8 + i];
            #pragma unroll
            for (int j = 0; j < 4; j++) w[j] = Ws[kk][tx * 4 + j];
            #pragma unroll
            for (int i = 0; i < 8; i++)
                #pragma unroll
                for (int j = 0; j < 4; j++)
                    acc[i][j] = fmaf(a[i], w[j], acc[i][j]);
        }
        __syncthreads();
    }

    #pragma unroll
    for (int j = 0; j < 4; j++) {
        float bval = be[n0 + tx * 4 + j];
        #pragma unroll
        for (int i = 0; i < 8; i++) {
            float v = acc[i][j] + bval;
            if (act == 0)      v = fmaxf(v, 0.f);
            else               v = 1.f / (1.f + expf(-v));
            C[e * cExpStride + (size_t)(m0 + ty * 8 + i) * ldc + n0 + tx * 4 + j] = v;
        }
    }
}

// ---------------- warp helpers ----------------
__device__ __forceinline__ float warp_allreduce(float v) {
    #pragma unroll
    for (int o = 16; o > 0; o >>= 1) v += __shfl_xor_sync(0xffffffffu, v, o);
    return v;
}

// ---------------- level-1 gates + combine ----------------
// gates: task t softmax over 4 (from X @ g1_Ws[t]), shared softmax over 6 (X @ g1_Wsh)
// writes g_X2[0]=task0, g_X2[1]=task1, g_X2[2]=shared   (each [B, 256])
__global__ void gate1_kernel(const float* __restrict__ Wst,  // [2,512,4]
                             const float* __restrict__ bst,  // [2,4]
                             const float* __restrict__ Wsh,  // [512,6]
                             const float* __restrict__ bsh)  // [6]
{
    int warp = threadIdx.x >> 5;
    int lane = threadIdx.x & 31;
    int b = blockIdx.x * 8 + warp;

    const float* x = g_X + (size_t)b * DIN;
    float xr[16];
    #pragma unroll
    for (int j = 0; j < 16; j++) xr[j] = x[lane + 32 * j];

    float logit[14];
    #pragma unroll
    for (int L = 0; L < 14; L++) {
        float acc = 0.f;
        if (L < 8) {
            int t = L >> 2, k = L & 3;
            const float* wc = Wst + (size_t)t * DIN * 4 + k;
            #pragma unroll
            for (int j = 0; j < 16; j++) acc += xr[j] * wc[(lane + 32 * j) * 4];
        } else {
            const float* wc = Wsh + (L - 8);
            #pragma unroll
            for (int j = 0; j < 16; j++) acc += xr[j] * wc[(lane + 32 * j) * 6];
        }
        acc = warp_allreduce(acc);
        logit[L] = acc + ((L < 8) ? bst[(L >> 2) * 4 + (L & 3)] : bsh[L - 8]);
    }

    // softmaxes (computed redundantly per lane; cheap)
    float g0[4], g1[4], gs[6];
    {
        float m = fmaxf(fmaxf(logit[0], logit[1]), fmaxf(logit[2], logit[3]));
        float s = 0.f;
        #pragma unroll
        for (int k = 0; k < 4; k++) { g0[k] = expf(logit[k] - m); s += g0[k]; }
        #pragma unroll
        for (int k = 0; k < 4; k++) g0[k] /= s;
    }
    {
        float m = fmaxf(fmaxf(logit[4], logit[5]), fmaxf(logit[6], logit[7]));
        float s = 0.f;
        #pragma unroll
        for (int k = 0; k < 4; k++) { g1[k] = expf(logit[4 + k] - m); s += g1[k]; }
        #pragma unroll
        for (int k = 0; k < 4; k++) g1[k] /= s;
    }
    {
        float m = logit[8];
        #pragma unroll
        for (int k = 9; k < 14; k++) m = fmaxf(m, logit[k]);
        float s = 0.f;
        #pragma unroll
        for (int k = 0; k < 6; k++) { gs[k] = expf(logit[8 + k] - m); s += gs[k]; }
        #pragma unroll
        for (int k = 0; k < 6; k++) gs[k] /= s;
    }

    #pragma unroll
    for (int it = 0; it < 8; it++) {
        int c = lane + 32 * it;
        float v[6];
        #pragma unroll
        for (int e = 0; e < 6; e++) v[e] = g_O[((size_t)e * B_ + b) * H2_ + c];
        float o0 = g0[0]*v[0] + g0[1]*v[1] + g0[2]*v[4] + g0[3]*v[5];
        float o1 = g1[0]*v[2] + g1[1]*v[3] + g1[2]*v[4] + g1[3]*v[5];
        float os = 0.f;
        #pragma unroll
        for (int e = 0; e < 6; e++) os += gs[e] * v[e];
        g_X2[((size_t)0 * B_ + b) * H2_ + c] = o0;
        g_X2[((size_t)1 * B_ + b) * H2_ + c] = o1;
        g_X2[((size_t)2 * B_ + b) * H2_ + c] = os;
    }
}

// ---------------- level-2 gates + combine ----------------
__global__ void gate2_kernel(const float* __restrict__ Wst,  // [2,256,4]
                             const float* __restrict__ bst)  // [2,4]
{
    int warp = threadIdx.x >> 5;
    int lane = threadIdx.x & 31;
    int b = blockIdx.x * 8 + warp;

    float x0r[8], x1r[8];
    const float* x0 = g_X2 + ((size_t)0 * B_ + b) * H2_;
    const float* x1 = g_X2 + ((size_t)1 * B_ + b) * H2_;
    #pragma unroll
    for (int j = 0; j < 8; j++) { x0r[j] = x0[lane + 32*j]; x1r[j] = x1[lane + 32*j]; }

    float logit[8];
    #pragma unroll
    for (int L = 0; L < 8; L++) {
        int t = L >> 2, k = L & 3;
        const float* wc = Wst + (size_t)t * H2_ * 4 + k;
        float acc = 0.f;
        if (t == 0) {
            #pragma unroll
            for (int j = 0; j < 8; j++) acc += x0r[j] * wc[(lane + 32*j) * 4];
        } else {
            #pragma unroll
            for (int j = 0; j < 8; j++) acc += x1r[j] * wc[(lane + 32*j) * 4];
        }
        acc = warp_allreduce(acc);
        logit[L] = acc + bst[t * 4 + k];
    }

    float g0[4], g1[4];
    {
        float m = fmaxf(fmaxf(logit[0], logit[1]), fmaxf(logit[2], logit[3]));
        float s = 0.f;
        #pragma unroll
        for (int k = 0; k < 4; k++) { g0[k] = expf(logit[k] - m); s += g0[k]; }
        #pragma unroll
        for (int k = 0; k < 4; k++) g0[k] /= s;
    }
    {
        float m = fmaxf(fmaxf(logit[4], logit[5]), fmaxf(logit[6], logit[7]));
        float s = 0.f;
        #pragma unroll
        for (int k = 0; k < 4; k++) { g1[k] = expf(logit[4 + k] - m); s += g1[k]; }
        #pragma unroll
        for (int k = 0; k < 4; k++) g1[k] /= s;
    }

    #pragma unroll
    for (int it = 0; it < 8; it++) {
        int c = lane + 32 * it;
        float v[6];
        #pragma unroll
        for (int e = 0; e < 6; e++) v[e] = g_O[((size_t)e * B_ + b) * H2_ + c];
        float o0 = g0[0]*v[0] + g0[1]*v[1] + g0[2]*v[4] + g0[3]*v[5];
        float o1 = g1[0]*v[2] + g1[1]*v[3] + g1[2]*v[4] + g1[3]*v[5];
        g_X3[((size_t)0 * B_ + b) * H2_ + c] = o0;
        g_X3[((size_t)1 * B_ + b) * H2_ + c] = o1;
    }
}

// ---------------- launcher ----------------
extern "C" void kernel_launch(void* const* d_in, const int* in_sizes, int n_in,
                              void* d_out, int out_size) {
    const int*   x_ids = (const int*)  d_in[0];
    const float* emb   = (const float*)d_in[1];
    const float* e1_W1 = (const float*)d_in[2];
    const float* e1_b1 = (const float*)d_in[3];
    const float* e1_W2 = (const float*)d_in[4];
    const float* e1_b2 = (const float*)d_in[5];
    const float* g1_Ws = (const float*)d_in[6];
    const float* g1_bs = (const float*)d_in[7];
    const float* g1_Wsh= (const float*)d_in[8];
    const float* g1_bsh= (const float*)d_in[9];
    const float* e2_W1 = (const float*)d_in[10];
    const float* e2_b1 = (const float*)d_in[11];
    const float* e2_W2 = (const float*)d_in[12];
    const float* e2_b2 = (const float*)d_in[13];
    const float* g2_Ws = (const float*)d_in[14];
    const float* g2_bs = (const float*)d_in[15];
    const float* tw_W1 = (const float*)d_in[16];
    const float* tw_b1 = (const float*)d_in[17];
    const float* tw_W2 = (const float*)d_in[18];
    const float* tw_b2 = (const float*)d_in[19];

    float *pX, *pH, *pO, *pX2, *pX3, *pT;
    cudaGetSymbolAddress((void**)&pX,  g_X);
    cudaGetSymbolAddress((void**)&pH,  g_H);
    cudaGetSymbolAddress((void**)&pO,  g_O);
    cudaGetSymbolAddress((void**)&pX2, g_X2);
    cudaGetSymbolAddress((void**)&pX3, g_X3);
    cudaGetSymbolAddress((void**)&pT,  g_T);

    // 1. embedding gather -> g_X [B,512]
    gather_kernel<<<(B_ * F_) / 256, 256>>>(x_ids, emb);

    // 2. level-1 experts stage 1: relu(X @ e1_W1[e]) -> g_H [6,B,512]   (shared A)
    gemm_kernel<<<dim3(H1_/BN, B_/BM, NE), 256>>>(pX, e1_W1, e1_b1, pH,
        B_, H1_, DIN, /*a_sel=*/0, (size_t)B_*H1_, H1_, /*relu*/0);

    // 3. level-1 experts stage 2: relu(H @ e1_W2[e]) -> g_O [6,B,256]
    gemm_kernel<<<dim3(H2_/BN, B_/BM, NE), 256>>>(pH, e1_W2, e1_b2, pO,
        B_, H2_, H1_, /*a_sel=*/2, (size_t)B_*H2_, H2_, 0);

    // 4. level-1 gates + combine -> g_X2 [3,B,256]
    gate1_kernel<<<B_/8, 256>>>(g1_Ws, g1_bs, g1_Wsh, g1_bsh);

    // 5. level-2 experts stage 1: relu(X2[e/2] @ e2_W1[e]) -> g_H [6,B,512]
    gemm_kernel<<<dim3(H1_/BN, B_/BM, NE), 256>>>(pX2, e2_W1, e2_b1, pH,
        B_, H1_, H2_, /*a_sel=*/1, (size_t)B_*H1_, H1_, 0);

    // 6. level-2 experts stage 2: relu(H @ e2_W2[e]) -> g_O [6,B,256]
    gemm_kernel<<<dim3(H2_/BN, B_/BM, NE), 256>>>(pH, e2_W2, e2_b2, pO,
        B_, H2_, H1_, /*a_sel=*/2, (size_t)B_*H2_, H2_, 0);

    // 7. level-2 gates + combine -> g_X3 [2,B,256]
    gate2_kernel<<<B_/8, 256>>>(g2_Ws, g2_bs);

    // 8. towers stage 1: relu(X3[t] @ tw_W1[t]) -> g_T [2,B,128]
    gemm_kernel<<<dim3(T1_/BN, B_/BM, 2), 256>>>(pX3, tw_W1, tw_b1, pT,
        B_, T1_, H2_, /*a_sel=*/2, (size_t)B_*T1_, T1_, 0);

    // 9. towers stage 2: sigmoid(T @ tw_W2[t]) -> d_out [B, 2*64] interleaved
    gemm_kernel<<<dim3(T2_/BN, B_/BM, 2), 256>>>(pT, tw_W2, tw_b2, (float*)d_out,
        B_, T2_, T1_, /*a_sel=*/2, /*cExpStride=*/(size_t)T2_, /*ldc=*/2*T2_, /*sigmoid*/1);
}

// round 3
// speedup vs baseline: 2.4362x; 2.4362x over previous
#include <cuda_runtime.h>
#include <cuda_bf16.h>
#include <math.h>
#include <stdint.h>

typedef __nv_bfloat16 bf16;

#define B_   16384
#define F_   32
#define V_   50000
#define DE   16
#define DIN  512
#define NE   6
#define H1_  512
#define H2_  256
#define T1_  128
#define T2_  64

// ---------------- scratch (device globals; no runtime alloc) ----------------
__device__ __align__(256) float g_X  [(size_t)B_*DIN];
__device__ __align__(256) bf16  g_Xh [(size_t)B_*DIN];
__device__ __align__(256) bf16  g_Xl [(size_t)B_*DIN];
__device__ __align__(256) bf16  g_Hh [(size_t)NE*B_*H1_];
__device__ __align__(256) bf16  g_Hl [(size_t)NE*B_*H1_];
__device__ __align__(256) float g_O  [(size_t)NE*B_*H2_];
__device__ __align__(256) float g_X2 [(size_t)3*B_*H2_];
__device__ __align__(256) bf16  g_X2h[(size_t)3*B_*H2_];
__device__ __align__(256) bf16  g_X2l[(size_t)3*B_*H2_];
__device__ __align__(256) bf16  g_X3h[(size_t)2*B_*H2_];
__device__ __align__(256) bf16  g_X3l[(size_t)2*B_*H2_];
__device__ __align__(256) bf16  g_Th [(size_t)2*B_*T1_];
__device__ __align__(256) bf16  g_Tl [(size_t)2*B_*T1_];
// transposed split weights, layout [E, N, K] (K-major rows)
__device__ __align__(256) bf16 g_w1h[(size_t)NE*H1_*DIN], g_w1l[(size_t)NE*H1_*DIN];
__device__ __align__(256) bf16 g_w2h[(size_t)NE*H2_*H1_], g_w2l[(size_t)NE*H2_*H1_];
__device__ __align__(256) bf16 g_w3h[(size_t)NE*H1_*H2_], g_w3l[(size_t)NE*H1_*H2_];
__device__ __align__(256) bf16 g_w4h[(size_t)NE*H2_*H1_], g_w4l[(size_t)NE*H2_*H1_];
__device__ __align__(256) bf16 g_w5h[(size_t)2*T1_*H2_], g_w5l[(size_t)2*T1_*H2_];
__device__ __align__(256) bf16 g_w6h[(size_t)2*T2_*T1_], g_w6l[(size_t)2*T2_*T1_];

// ---------------- helpers ----------------
__device__ __forceinline__ uint32_t smem_u32(const void* p) {
    uint32_t a;
    asm("{ .reg .u64 t; cvta.to.shared.u64 t, %1; cvt.u32.u64 %0, t; }" : "=r"(a) : "l"(p));
    return a;
}
__device__ __forceinline__ void cp16(uint32_t dst, const void* src) {
    asm volatile("cp.async.cg.shared.global [%0], [%1], 16;" :: "r"(dst), "l"(src));
}
__device__ __forceinline__ void ldsm4(uint32_t* r, uint32_t a) {
    asm volatile("ldmatrix.sync.aligned.m8n8.x4.shared.b16 {%0,%1,%2,%3}, [%4];"
                 : "=r"(r[0]), "=r"(r[1]), "=r"(r[2]), "=r"(r[3]) : "r"(a));
}
__device__ __forceinline__ void mma16816(float* c, const uint32_t* a, const uint32_t* b) {
    asm volatile("mma.sync.aligned.m16n8k16.row.col.f32.bf16.bf16.f32 "
                 "{%0,%1,%2,%3}, {%4,%5,%6,%7}, {%8,%9}, {%0,%1,%2,%3};"
                 : "+f"(c[0]), "+f"(c[1]), "+f"(c[2]), "+f"(c[3])
                 : "r"(a[0]), "r"(a[1]), "r"(a[2]), "r"(a[3]), "r"(b[0]), "r"(b[1]));
}
__device__ __forceinline__ uint32_t swz(uint32_t off) { return off ^ ((off >> 3) & 0x70); }

// ---------------- split-precision mma.sync grouped GEMM ----------------
// C[e] = act(A[aidx] @ B[e]^T + bias[e])
// A: [*, K] bf16 hi/lo row-major; B: [E, Ntot, K] bf16 hi/lo (K-major rows)
// NT: CTA N-tile (128 or 64). ACT: 0=relu 1=sigmoid. OUTM: 0=f32, 1=bf16 hi/lo split.
template<int NT, int ACT, int OUTM>
__global__ void __launch_bounds__(256, 1)
gemm_mma(const bf16* __restrict__ Ah, const bf16* __restrict__ Al,
         const bf16* __restrict__ Bh, const bf16* __restrict__ Bl,
         const float* __restrict__ bias,
         float* __restrict__ Cf, bf16* __restrict__ Ch, bf16* __restrict__ Cl,
         int K, int Ntot, int a_sel, size_t aStride, size_t cStride, int ldc)
{
    extern __shared__ char smem_raw[];
    constexpr int ASTG  = 128 * 128;         // one A matrix (hi or lo) per stage: 128 rows x 128B
    constexpr int BSTG  = NT * 128;
    constexpr int STAGE = 2 * ASTG + 2 * BSTG;
    constexpr int NJ    = NT / 32;           // n8 tiles per warp

    const int tid  = threadIdx.x;
    const int wid  = tid >> 5;
    const int lane = tid & 31;
    const int e  = blockIdx.z;
    const int m0 = blockIdx.y * 128;
    const int n0 = blockIdx.x * NT;

    const int aidx = (a_sel == 0) ? 0 : ((a_sel == 1) ? (e >> 1) : e);
    const bf16* pAh = Ah + (size_t)aidx * aStride + (size_t)m0 * K;
    const bf16* pAl = Al + (size_t)aidx * aStride + (size_t)m0 * K;
    const bf16* pBh = Bh + ((size_t)e * Ntot + n0) * K;
    const bf16* pBl = Bl + ((size_t)e * Ntot + n0) * K;

    const uint32_t sb = smem_u32(smem_raw);

    // warp tiling: 2 x 4 warp grid; warp tile 64 x (NT/4)
    const int wm = wid >> 2, wn = wid & 3;
    const int mw = wm * 64;
    const int nw = wn * (NT / 4);

    float acc[4][NJ][4];
    #pragma unroll
    for (int i = 0; i < 4; i++)
        #pragma unroll
        for (int j = 0; j < NJ; j++)
            #pragma unroll
            for (int q = 0; q < 4; q++) acc[i][j][q] = 0.f;

    auto load_stage = [&](int kt, int st) {
        const uint32_t base = sb + st * STAGE;
        const int k0 = kt * 64;
        #pragma unroll
        for (int t = 0; t < 4; t++) {                 // A: 128 rows x 8 chunks / 256 thr
            int id = tid + t * 256;
            int r = id >> 3, q = id & 7;
            uint32_t off = swz((uint32_t)(r * 128 + q * 16));
            cp16(base + off,         pAh + (size_t)r * K + k0 + q * 8);
            cp16(base + ASTG + off,  pAl + (size_t)r * K + k0 + q * 8);
        }
        #pragma unroll
        for (int t = 0; t < NT / 32; t++) {           // B: NT rows x 8 chunks / 256 thr
            int id = tid + t * 256;
            int r = id >> 3, q = id & 7;
            uint32_t off = swz((uint32_t)(r * 128 + q * 16));
            cp16(base + 2 * ASTG + off,        pBh + (size_t)r * K + k0 + q * 8);
            cp16(base + 2 * ASTG + BSTG + off, pBl + (size_t)r * K + k0 + q * 8);
        }
        asm volatile("cp.async.commit_group;" ::: "memory");
    };

    load_stage(0, 0);
    const int T = K >> 6;
    for (int kt = 0; kt < T; kt++) {
        if (kt + 1 < T) {
            load_stage(kt + 1, (kt + 1) & 1);
            asm volatile("cp.async.wait_group 1;" ::: "memory");
        } else {
            asm volatile("cp.async.wait_group 0;" ::: "memory");
        }
        __syncthreads();

        const uint32_t abase = sb + (kt & 1) * STAGE;
        const uint32_t bbase = abase + 2 * ASTG;

        #pragma unroll
        for (int ks = 0; ks < 4; ks++) {
            const int cb = ks * 32 + (lane >> 4) * 16;
            uint32_t ahf[4][4], alf[4][4];
            #pragma unroll
            for (int i = 0; i < 4; i++) {
                int row = mw + i * 16 + (lane & 15);
                uint32_t off = swz((uint32_t)(row * 128 + cb));
                ldsm4(ahf[i], abase + off);
                ldsm4(alf[i], abase + ASTG + off);
            }
            uint32_t bhf[NJ][2], blf[NJ][2];
            #pragma unroll
            for (int bb = 0; bb < NT / 64; bb++) {
                int row = nw + bb * 16 + (lane & 15);
                uint32_t off = swz((uint32_t)(row * 128 + cb));
                uint32_t tr[4];
                ldsm4(tr, bbase + off);
                bhf[2*bb][0] = tr[0]; bhf[2*bb+1][0] = tr[1];
                bhf[2*bb][1] = tr[2]; bhf[2*bb+1][1] = tr[3];
                ldsm4(tr, bbase + BSTG + off);
                blf[2*bb][0] = tr[0]; blf[2*bb+1][0] = tr[1];
                blf[2*bb][1] = tr[2]; blf[2*bb+1][1] = tr[3];
            }
            #pragma unroll
            for (int i = 0; i < 4; i++)
                #pragma unroll
                for (int j = 0; j < NJ; j++) {
                    mma16816(acc[i][j], ahf[i], bhf[j]);   // hi*hi
                    mma16816(acc[i][j], ahf[i], blf[j]);   // hi*lo
                    mma16816(acc[i][j], alf[i], bhf[j]);   // lo*hi
                }
        }
        __syncthreads();
    }

    // ---------------- epilogue: bias + act + store ----------------
    const int lr  = lane >> 2;
    const int lc2 = (lane & 3) * 2;
    #pragma unroll
    for (int i = 0; i < 4; i++)
        #pragma unroll
        for (int j = 0; j < NJ; j++) {
            int col = n0 + nw + j * 8 + lc2;
            float b0 = __ldg(bias + (size_t)e * Ntot + col);
            float b1 = __ldg(bias + (size_t)e * Ntot + col + 1);
            #pragma unroll
            for (int h = 0; h < 2; h++) {
                int row = m0 + mw + i * 16 + lr + h * 8;
                float v0 = acc[i][j][2 * h + 0] + b0;
                float v1 = acc[i][j][2 * h + 1] + b1;
                if (ACT == 0) { v0 = fmaxf(v0, 0.f); v1 = fmaxf(v1, 0.f); }
                else { v0 = 1.f / (1.f + __expf(-v0)); v1 = 1.f / (1.f + __expf(-v1)); }
                size_t gi = (size_t)e * cStride + (size_t)row * ldc + col;
                if (OUTM == 0) {
                    *reinterpret_cast<float2*>(Cf + gi) = make_float2(v0, v1);
                } else {
                    bf16 h0 = __float2bfloat16(v0), h1 = __float2bfloat16(v1);
                    __nv_bfloat162 hv; hv.x = h0; hv.y = h1;
                    __nv_bfloat162 lv;
                    lv.x = __float2bfloat16(v0 - __bfloat162float(h0));
                    lv.y = __float2bfloat16(v1 - __bfloat162float(h1));
                    *reinterpret_cast<__nv_bfloat162*>(Ch + gi) = hv;
                    *reinterpret_cast<__nv_bfloat162*>(Cl + gi) = lv;
                }
            }
        }
}

// ---------------- embedding gather + split ----------------
__global__ void gather_kernel(const int* __restrict__ ids, const float* __restrict__ emb) {
    int idx = blockIdx.x * blockDim.x + threadIdx.x;   // b*F + f
    if (idx >= B_ * F_) return;
    int f  = idx & (F_ - 1);
    int id = ids[idx];
    const float4* src = reinterpret_cast<const float4*>(emb + ((size_t)f * V_ + id) * DE);
    float4 v0 = src[0], v1 = src[1], v2 = src[2], v3 = src[3];
    float4* dst = reinterpret_cast<float4*>(g_X + (size_t)idx * DE);
    dst[0] = v0; dst[1] = v1; dst[2] = v2; dst[3] = v3;

    float vals[16] = {v0.x,v0.y,v0.z,v0.w, v1.x,v1.y,v1.z,v1.w,
                      v2.x,v2.y,v2.z,v2.w, v3.x,v3.y,v3.z,v3.w};
    __align__(16) bf16 hi[16], lo[16];
    #pragma unroll
    for (int j = 0; j < 16; j++) {
        bf16 h = __float2bfloat16(vals[j]);
        hi[j] = h;
        lo[j] = __float2bfloat16(vals[j] - __bfloat162float(h));
    }
    uint4* dh = reinterpret_cast<uint4*>(g_Xh + (size_t)idx * DE);
    uint4* dl = reinterpret_cast<uint4*>(g_Xl + (size_t)idx * DE);
    dh[0] = ((uint4*)hi)[0]; dh[1] = ((uint4*)hi)[1];
    dl[0] = ((uint4*)lo)[0]; dl[1] = ((uint4*)lo)[1];
}

// ---------------- weight transpose + split: W[E,K,N] -> T[E,N,K] hi/lo ----------------
__global__ void wsplit_kernel(const float* __restrict__ W, bf16* __restrict__ Th,
                              bf16* __restrict__ Tl, int K, int N) {
    __shared__ float t[32][33];
    int e = blockIdx.z, n0 = blockIdx.x * 32, k0 = blockIdx.y * 32;
    int tx = threadIdx.x, ty = threadIdx.y;
    #pragma unroll
    for (int j = 0; j < 4; j++)
        t[ty + 8 * j][tx] = W[((size_t)e * K + k0 + ty + 8 * j) * N + n0 + tx];
    __syncthreads();
    #pragma unroll
    for (int j = 0; j < 4; j++) {
        int n = n0 + ty + 8 * j, k = k0 + tx;
        float v = t[tx][ty + 8 * j];
        bf16 h = __float2bfloat16(v);
        Th[((size_t)e * N + n) * K + k] = h;
        Tl[((size_t)e * N + n) * K + k] = __float2bfloat16(v - __bfloat162float(h));
    }
}

// ---------------- warp helpers ----------------
__device__ __forceinline__ float warp_allreduce(float v) {
    #pragma unroll
    for (int o = 16; o > 0; o >>= 1) v += __shfl_xor_sync(0xffffffffu, v, o);
    return v;
}

// ---------------- level-1 gates + combine ----------------
__global__ void gate1_kernel(const float* __restrict__ Wst, const float* __restrict__ bst,
                             const float* __restrict__ Wsh, const float* __restrict__ bsh)
{
    int warp = threadIdx.x >> 5, lane = threadIdx.x & 31;
    int b = blockIdx.x * 8 + warp;

    const float* x = g_X + (size_t)b * DIN;
    float xr[16];
    #pragma unroll
    for (int j = 0; j < 16; j++) xr[j] = x[lane + 32 * j];

    float logit[14];
    #pragma unroll
    for (int L = 0; L < 14; L++) {
        float acc = 0.f;
        if (L < 8) {
            int t = L >> 2, k = L & 3;
            const float* wc = Wst + (size_t)t * DIN * 4 + k;
            #pragma unroll
            for (int j = 0; j < 16; j++) acc += xr[j] * wc[(lane + 32 * j) * 4];
        } else {
            const float* wc = Wsh + (L - 8);
            #pragma unroll
            for (int j = 0; j < 16; j++) acc += xr[j] * wc[(lane + 32 * j) * 6];
        }
        acc = warp_allreduce(acc);
        logit[L] = acc + ((L < 8) ? bst[(L >> 2) * 4 + (L & 3)] : bsh[L - 8]);
    }

    float g0[4], g1[4], gs[6];
    {
        float m = fmaxf(fmaxf(logit[0], logit[1]), fmaxf(logit[2], logit[3]));
        float s = 0.f;
        #pragma unroll
        for (int k = 0; k < 4; k++) { g0[k] = expf(logit[k] - m); s += g0[k]; }
        #pragma unroll
        for (int k = 0; k < 4; k++) g0[k] /= s;
    }
    {
        float m = fmaxf(fmaxf(logit[4], logit[5]), fmaxf(logit[6], logit[7]));
        float s = 0.f;
        #pragma unroll
        for (int k = 0; k < 4; k++) { g1[k] = expf(logit[4 + k] - m); s += g1[k]; }
        #pragma unroll
        for (int k = 0; k < 4; k++) g1[k] /= s;
    }
    {
        float m = logit[8];
        #pragma unroll
        for (int k = 9; k < 14; k++) m = fmaxf(m, logit[k]);
        float s = 0.f;
        #pragma unroll
        for (int k = 0; k < 6; k++) { gs[k] = expf(logit[8 + k] - m); s += gs[k]; }
        #pragma unroll
        for (int k = 0; k < 6; k++) gs[k] /= s;
    }

    #pragma unroll
    for (int it = 0; it < 8; it++) {
        int c = lane + 32 * it;
        float v[6];
        #pragma unroll
        for (int e = 0; e < 6; e++) v[e] = g_O[((size_t)e * B_ + b) * H2_ + c];
        float o0 = g0[0]*v[0] + g0[1]*v[1] + g0[2]*v[4] + g0[3]*v[5];
        float o1 = g1[0]*v[2] + g1[1]*v[3] + g1[2]*v[4] + g1[3]*v[5];
        float os = 0.f;
        #pragma unroll
        for (int e = 0; e < 6; e++) os += gs[e] * v[e];
        size_t i0 = ((size_t)0 * B_ + b) * H2_ + c;
        size_t i1 = ((size_t)1 * B_ + b) * H2_ + c;
        size_t i2 = ((size_t)2 * B_ + b) * H2_ + c;
        g_X2[i0] = o0; g_X2[i1] = o1; g_X2[i2] = os;
        bf16 h;
        h = __float2bfloat16(o0); g_X2h[i0] = h; g_X2l[i0] = __float2bfloat16(o0 - __bfloat162float(h));
        h = __float2bfloat16(o1); g_X2h[i1] = h; g_X2l[i1] = __float2bfloat16(o1 - __bfloat162float(h));
        h = __float2bfloat16(os); g_X2h[i2] = h; g_X2l[i2] = __float2bfloat16(os - __bfloat162float(h));
    }
}

// ---------------- level-2 gates + combine ----------------
__global__ void gate2_kernel(const float* __restrict__ Wst, const float* __restrict__ bst)
{
    int warp = threadIdx.x >> 5, lane = threadIdx.x & 31;
    int b = blockIdx.x * 8 + warp;

    float x0r[8], x1r[8];
    const float* x0 = g_X2 + ((size_t)0 * B_ + b) * H2_;
    const float* x1 = g_X2 + ((size_t)1 * B_ + b) * H2_;
    #pragma unroll
    for (int j = 0; j < 8; j++) { x0r[j] = x0[lane + 32*j]; x1r[j] = x1[lane + 32*j]; }

    float logit[8];
    #pragma unroll
    for (int L = 0; L < 8; L++) {
        int t = L >> 2, k = L & 3;
        const float* wc = Wst + (size_t)t * H2_ * 4 + k;
        float acc = 0.f;
        if (t == 0) {
            #pragma unroll
            for (int j = 0; j < 8; j++) acc += x0r[j] * wc[(lane + 32*j) * 4];
        } else {
            #pragma unroll
            for (int j = 0; j < 8; j++) acc += x1r[j] * wc[(lane + 32*j) * 4];
        }
        acc = warp_allreduce(acc);
        logit[L] = acc + bst[t * 4 + k];
    }

    float g0[4], g1[4];
    {
        float m = fmaxf(fmaxf(logit[0], logit[1]), fmaxf(logit[2], logit[3]));
        float s = 0.f;
        #pragma unroll
        for (int k = 0; k < 4; k++) { g0[k] = expf(logit[k] - m); s += g0[k]; }
        #pragma unroll
        for (int k = 0; k < 4; k++) g0[k] /= s;
    }
    {
        float m = fmaxf(fmaxf(logit[4], logit[5]), fmaxf(logit[6], logit[7]));
        float s = 0.f;
        #pragma unroll
        for (int k = 0; k < 4; k++) { g1[k] = expf(logit[4 + k] - m); s += g1[k]; }
        #pragma unroll
        for (int k = 0; k < 4; k++) g1[k] /= s;
    }

    #pragma unroll
    for (int it = 0; it < 8; it++) {
        int c = lane + 32 * it;
        float v[6];
        #pragma unroll
        for (int e = 0; e < 6; e++) v[e] = g_O[((size_t)e * B_ + b) * H2_ + c];
        float o0 = g0[0]*v[0] + g0[1]*v[1] + g0[2]*v[4] + g0[3]*v[5];
        float o1 = g1[0]*v[2] + g1[1]*v[3] + g1[2]*v[4] + g1[3]*v[5];
        size_t i0 = ((size_t)0 * B_ + b) * H2_ + c;
        size_t i1 = ((size_t)1 * B_ + b) * H2_ + c;
        bf16 h;
        h = __float2bfloat16(o0); g_X3h[i0] = h; g_X3l[i0] = __float2bfloat16(o0 - __bfloat162float(h));
        h = __float2bfloat16(o1); g_X3h[i1] = h; g_X3l[i1] = __float2bfloat16(o1 - __bfloat162float(h));
    }
}

// ---------------- launcher ----------------
extern "C" void kernel_launch(void* const* d_in, const int* in_sizes, int n_in,
                              void* d_out, int out_size) {
    const int*   x_ids = (const int*)  d_in[0];
    const float* emb   = (const float*)d_in[1];
    const float* e1_W1 = (const float*)d_in[2];
    const float* e1_b1 = (const float*)d_in[3];
    const float* e1_W2 = (const float*)d_in[4];
    const float* e1_b2 = (const float*)d_in[5];
    const float* g1_Ws = (const float*)d_in[6];
    const float* g1_bs = (const float*)d_in[7];
    const float* g1_Wsh= (const float*)d_in[8];
    const float* g1_bsh= (const float*)d_in[9];
    const float* e2_W1 = (const float*)d_in[10];
    const float* e2_b1 = (const float*)d_in[11];
    const float* e2_W2 = (const float*)d_in[12];
    const float* e2_b2 = (const float*)d_in[13];
    const float* g2_Ws = (const float*)d_in[14];
    const float* g2_bs = (const float*)d_in[15];
    const float* tw_W1 = (const float*)d_in[16];
    const float* tw_b1 = (const float*)d_in[17];
    const float* tw_W2 = (const float*)d_in[18];
    const float* tw_b2 = (const float*)d_in[19];

    bf16 *pXh,*pXl,*pHh,*pHl,*pX2h,*pX2l,*pX3h,*pX3l,*pTh,*pTl;
    bf16 *w1h,*w1l,*w2h,*w2l,*w3h,*w3l,*w4h,*w4l,*w5h,*w5l,*w6h,*w6l;
    cudaGetSymbolAddress((void**)&pXh, g_Xh);   cudaGetSymbolAddress((void**)&pXl, g_Xl);
    cudaGetSymbolAddress((void**)&pHh, g_Hh);   cudaGetSymbolAddress((void**)&pHl, g_Hl);
    cudaGetSymbolAddress((void**)&pX2h, g_X2h); cudaGetSymbolAddress((void**)&pX2l, g_X2l);
    cudaGetSymbolAddress((void**)&pX3h, g_X3h); cudaGetSymbolAddress((void**)&pX3l, g_X3l);
    cudaGetSymbolAddress((void**)&pTh, g_Th);   cudaGetSymbolAddress((void**)&pTl, g_Tl);
    cudaGetSymbolAddress((void**)&w1h, g_w1h);  cudaGetSymbolAddress((void**)&w1l, g_w1l);
    cudaGetSymbolAddress((void**)&w2h, g_w2h);  cudaGetSymbolAddress((void**)&w2l, g_w2l);
    cudaGetSymbolAddress((void**)&w3h, g_w3h);  cudaGetSymbolAddress((void**)&w3l, g_w3l);
    cudaGetSymbolAddress((void**)&w4h, g_w4h);  cudaGetSymbolAddress((void**)&w4l, g_w4l);
    cudaGetSymbolAddress((void**)&w5h, g_w5h);  cudaGetSymbolAddress((void**)&w5l, g_w5l);
    cudaGetSymbolAddress((void**)&w6h, g_w6h);  cudaGetSymbolAddress((void**)&w6l, g_w6l);
    float *pO;
    cudaGetSymbolAddress((void**)&pO, g_O);

    const int SM128 = 2 * (2 * 128 * 128 + 2 * 128 * 128);   // 131072
    const int SM64  = 2 * (2 * 128 * 128 + 2 * 64 * 128);    //  98304
    cudaFuncSetAttribute((const void*)gemm_mma<128,0,1>, cudaFuncAttributeMaxDynamicSharedMemorySize, SM128);
    cudaFuncSetAttribute((const void*)gemm_mma<128,0,0>, cudaFuncAttributeMaxDynamicSharedMemorySize, SM128);
    cudaFuncSetAttribute((const void*)gemm_mma<64,1,0>,  cudaFuncAttributeMaxDynamicSharedMemorySize, SM64);

    dim3 tb(32, 8);
    // weight prep (transpose + bf16 split)
    wsplit_kernel<<<dim3(H1_/32, DIN/32, NE), tb>>>(e1_W1, w1h, w1l, DIN, H1_);
    wsplit_kernel<<<dim3(H2_/32, H1_/32, NE), tb>>>(e1_W2, w2h, w2l, H1_, H2_);
    wsplit_kernel<<<dim3(H1_/32, H2_/32, NE), tb>>>(e2_W1, w3h, w3l, H2_, H1_);
    wsplit_kernel<<<dim3(H2_/32, H1_/32, NE), tb>>>(e2_W2, w4h, w4l, H1_, H2_);
    wsplit_kernel<<<dim3(T1_/32, H2_/32, 2),  tb>>>(tw_W1, w5h, w5l, H2_, T1_);
    wsplit_kernel<<<dim3(T2_/32, T1_/32, 2),  tb>>>(tw_W2, w6h, w6l, T1_, T2_);

    // embedding gather + split
    gather_kernel<<<(B_ * F_) / 256, 256>>>(x_ids, emb);

    // L1 experts stage 1: relu(X @ W1) -> H hi/lo   (shared A)
    gemm_mma<128,0,1><<<dim3(H1_/128, B_/128, NE), 256, SM128>>>(
        pXh, pXl, w1h, w1l, e1_b1, nullptr, pHh, pHl,
        DIN, H1_, 0, 0, (size_t)B_*H1_, H1_);
    // L1 experts stage 2: relu(H @ W2) -> O fp32
    gemm_mma<128,0,0><<<dim3(H2_/128, B_/128, NE), 256, SM128>>>(
        pHh, pHl, w2h, w2l, e1_b2, pO, nullptr, nullptr,
        H1_, H2_, 2, (size_t)B_*H1_, (size_t)B_*H2_, H2_);
    // L1 gates + combine -> X2 fp32 + hi/lo
    gate1_kernel<<<B_/8, 256>>>(g1_Ws, g1_bs, g1_Wsh, g1_bsh);

    // L2 experts stage 1: relu(X2[e/2] @ W1) -> H hi/lo
    gemm_mma<128,0,1><<<dim3(H1_/128, B_/128, NE), 256, SM128>>>(
        pX2h, pX2l, w3h, w3l, e2_b1, nullptr, pHh, pHl,
        H2_, H1_, 1, (size_t)B_*H2_, (size_t)B_*H1_, H1_);
    // L2 experts stage 2: relu(H @ W2) -> O fp32
    gemm_mma<128,0,0><<<dim3(H2_/128, B_/128, NE), 256, SM128>>>(
        pHh, pHl, w4h, w4l, e2_b2, pO, nullptr, nullptr,
        H1_, H2_, 2, (size_t)B_*H1_, (size_t)B_*H2_, H2_);
    // L2 gates + combine -> X3 hi/lo
    gate2_kernel<<<B_/8, 256>>>(g2_Ws, g2_bs);

    // tower stage 1: relu(X3[t] @ tw_W1) -> T hi/lo
    gemm_mma<128,0,1><<<dim3(T1_/128, B_/128, 2), 256, SM128>>>(
        pX3h, pX3l, w5h, w5l, tw_b1, nullptr, pTh, pTl,
        H2_, T1_, 2, (size_t)B_*H2_, (size_t)B_*T1_, T1_);
    // tower stage 2: sigmoid(T @ tw_W2) -> d_out [B, 2*64]
    gemm_mma<64,1,0><<<dim3(T2_/64, B_/128, 2), 256, SM64>>>(
        pTh, pTl, w6h, w6l, tw_b2, (float*)d_out, nullptr, nullptr,
        T1_, T2_, 2, (size_t)B_*T1_, (size_t)T2_, 2*T2_);
}

// round 4
// speedup vs baseline: 2.4518x; 1.0064x over previous
#include <cuda_runtime.h>
#include <cuda_bf16.h>
#include <math.h>
#include <stdint.h>

typedef __nv_bfloat16 bf16;

#define B_   16384
#define F_   32
#define V_   50000
#define DE   16
#define DIN  512
#define NE   6
#define H1_  512
#define H2_  256
#define T1_  128
#define T2_  64

// ---------------- scratch (device globals; no runtime alloc) ----------------
__device__ __align__(256) bf16  g_Xh [(size_t)B_*DIN];
__device__ __align__(256) bf16  g_Xl [(size_t)B_*DIN];
__device__ __align__(256) bf16  g_Hh [(size_t)NE*B_*H1_];
__device__ __align__(256) bf16  g_Hl [(size_t)NE*B_*H1_];
__device__ __align__(256) float g_O  [(size_t)NE*B_*H2_];
__device__ __align__(256) bf16  g_X2h[(size_t)3*B_*H2_];
__device__ __align__(256) bf16  g_X2l[(size_t)3*B_*H2_];
__device__ __align__(256) bf16  g_X3h[(size_t)2*B_*H2_];
__device__ __align__(256) bf16  g_X3l[(size_t)2*B_*H2_];
__device__ __align__(256) bf16  g_Th [(size_t)2*B_*T1_];
__device__ __align__(256) bf16  g_Tl [(size_t)2*B_*T1_];
// transposed split weights, layout [E, N, K] (K-major rows)
__device__ __align__(256) bf16 g_w1h[(size_t)NE*H1_*DIN], g_w1l[(size_t)NE*H1_*DIN];
__device__ __align__(256) bf16 g_w2h[(size_t)NE*H2_*H1_], g_w2l[(size_t)NE*H2_*H1_];
__device__ __align__(256) bf16 g_w3h[(size_t)NE*H1_*H2_], g_w3l[(size_t)NE*H1_*H2_];
__device__ __align__(256) bf16 g_w4h[(size_t)NE*H2_*H1_], g_w4l[(size_t)NE*H2_*H1_];
__device__ __align__(256) bf16 g_w5h[(size_t)2*T1_*H2_], g_w5l[(size_t)2*T1_*H2_];
__device__ __align__(256) bf16 g_w6h[(size_t)2*T2_*T1_], g_w6l[(size_t)2*T2_*T1_];

// ---------------- helpers ----------------
__device__ __forceinline__ uint32_t smem_u32(const void* p) {
    uint32_t a;
    asm("{ .reg .u64 t; cvta.to.shared.u64 t, %1; cvt.u32.u64 %0, t; }" : "=r"(a) : "l"(p));
    return a;
}
__device__ __forceinline__ void cp16(uint32_t dst, const void* src) {
    asm volatile("cp.async.cg.shared.global [%0], [%1], 16;" :: "r"(dst), "l"(src));
}
__device__ __forceinline__ void ldsm4(uint32_t* r, uint32_t a) {
    asm volatile("ldmatrix.sync.aligned.m8n8.x4.shared.b16 {%0,%1,%2,%3}, [%4];"
                 : "=r"(r[0]), "=r"(r[1]), "=r"(r[2]), "=r"(r[3]) : "r"(a));
}
__device__ __forceinline__ void mma16816(float* c, const uint32_t* a, const uint32_t* b) {
    asm volatile("mma.sync.aligned.m16n8k16.row.col.f32.bf16.bf16.f32 "
                 "{%0,%1,%2,%3}, {%4,%5,%6,%7}, {%8,%9}, {%0,%1,%2,%3};"
                 : "+f"(c[0]), "+f"(c[1]), "+f"(c[2]), "+f"(c[3])
                 : "r"(a[0]), "r"(a[1]), "r"(a[2]), "r"(a[3]), "r"(b[0]), "r"(b[1]));
}
__device__ __forceinline__ uint32_t swz(uint32_t off) { return off ^ ((off >> 3) & 0x70); }

// ---------------- split-precision mma.sync grouped GEMM ----------------
// C[e] = act(A[aidx] @ B[e]^T + bias[e])
// A: [*, K] bf16 hi/lo row-major; B: [E, Ntot, K] bf16 hi/lo (K-major rows)
// NT: CTA N-tile (128 or 64). ACT: 0=relu 1=sigmoid. OUTM: 0=f32, 1=bf16 hi/lo split.
template<int NT, int ACT, int OUTM>
__global__ void __launch_bounds__(256, 1)
gemm_mma(const bf16* __restrict__ Ah, const bf16* __restrict__ Al,
         const bf16* __restrict__ Bh, const bf16* __restrict__ Bl,
         const float* __restrict__ bias,
         float* __restrict__ Cf, bf16* __restrict__ Ch, bf16* __restrict__ Cl,
         int K, int Ntot, int a_sel, size_t aStride, size_t cStride, int ldc)
{
    extern __shared__ char smem_raw[];
    constexpr int ASTG  = 128 * 128;         // one A matrix (hi or lo) per stage
    constexpr int BSTG  = NT * 128;
    constexpr int STAGE = 2 * ASTG + 2 * BSTG;
    constexpr int NJ    = NT / 32;           // n8 tiles per warp

    const int tid  = threadIdx.x;
    const int wid  = tid >> 5;
    const int lane = tid & 31;
    const int e  = blockIdx.z;
    const int m0 = blockIdx.y * 128;
    const int n0 = blockIdx.x * NT;

    const int aidx = (a_sel == 0) ? 0 : ((a_sel == 1) ? (e >> 1) : e);
    const bf16* pAh = Ah + (size_t)aidx * aStride + (size_t)m0 * K;
    const bf16* pAl = Al + (size_t)aidx * aStride + (size_t)m0 * K;
    const bf16* pBh = Bh + ((size_t)e * Ntot + n0) * K;
    const bf16* pBl = Bl + ((size_t)e * Ntot + n0) * K;

    const uint32_t sb = smem_u32(smem_raw);

    // warp tiling: 2 x 4 warp grid; warp tile 64 x (NT/4)
    const int wm = wid >> 2, wn = wid & 3;
    const int mw = wm * 64;
    const int nw = wn * (NT / 4);

    float acc[4][NJ][4];
    #pragma unroll
    for (int i = 0; i < 4; i++)
        #pragma unroll
        for (int j = 0; j < NJ; j++)
            #pragma unroll
            for (int q = 0; q < 4; q++) acc[i][j][q] = 0.f;

    auto load_stage = [&](int kt, int st) {
        const uint32_t base = sb + st * STAGE;
        const int k0 = kt * 64;
        #pragma unroll
        for (int t = 0; t < 4; t++) {                 // A: 128 rows x 8 chunks / 256 thr
            int id = tid + t * 256;
            int r = id >> 3, q = id & 7;
            uint32_t off = swz((uint32_t)(r * 128 + q * 16));
            cp16(base + off,         pAh + (size_t)r * K + k0 + q * 8);
            cp16(base + ASTG + off,  pAl + (size_t)r * K + k0 + q * 8);
        }
        #pragma unroll
        for (int t = 0; t < NT / 32; t++) {           // B: NT rows x 8 chunks / 256 thr
            int id = tid + t * 256;
            int r = id >> 3, q = id & 7;
            uint32_t off = swz((uint32_t)(r * 128 + q * 16));
            cp16(base + 2 * ASTG + off,        pBh + (size_t)r * K + k0 + q * 8);
            cp16(base + 2 * ASTG + BSTG + off, pBl + (size_t)r * K + k0 + q * 8);
        }
        asm volatile("cp.async.commit_group;" ::: "memory");
    };

    // register fragment double buffers
    uint32_t ahf[2][4][4], alf[2][4][4];
    uint32_t bhf[2][NJ][2], blf[2][NJ][2];

    auto load_frags = [&](uint32_t abase, uint32_t bbase, int ks, int pb) {
        const int cb = ks * 32 + (lane >> 4) * 16;
        #pragma unroll
        for (int i = 0; i < 4; i++) {
            int row = mw + i * 16 + (lane & 15);
            uint32_t off = swz((uint32_t)(row * 128 + cb));
            ldsm4(ahf[pb][i], abase + off);
            ldsm4(alf[pb][i], abase + ASTG + off);
        }
        #pragma unroll
        for (int bb = 0; bb < NT / 64; bb++) {
            int row = nw + bb * 16 + (lane & 15);
            uint32_t off = swz((uint32_t)(row * 128 + cb));
            uint32_t tr[4];
            ldsm4(tr, bbase + off);
            bhf[pb][2*bb][0] = tr[0]; bhf[pb][2*bb+1][0] = tr[1];
            bhf[pb][2*bb][1] = tr[2]; bhf[pb][2*bb+1][1] = tr[3];
            ldsm4(tr, bbase + BSTG + off);
            blf[pb][2*bb][0] = tr[0]; blf[pb][2*bb+1][0] = tr[1];
            blf[pb][2*bb][1] = tr[2]; blf[pb][2*bb+1][1] = tr[3];
        }
    };

    load_stage(0, 0);
    const int T = K >> 6;
    for (int kt = 0; kt < T; kt++) {
        if (kt + 1 < T) {
            load_stage(kt + 1, (kt + 1) & 1);
            asm volatile("cp.async.wait_group 1;" ::: "memory");
        } else {
            asm volatile("cp.async.wait_group 0;" ::: "memory");
        }
        __syncthreads();

        const uint32_t abase = sb + (kt & 1) * STAGE;
        const uint32_t bbase = abase + 2 * ASTG;

        load_frags(abase, bbase, 0, 0);
        #pragma unroll
        for (int ks = 0; ks < 4; ks++) {
            const int pb = ks & 1;
            if (ks < 3) load_frags(abase, bbase, ks + 1, pb ^ 1);   // prefetch next step
            #pragma unroll
            for (int i = 0; i < 4; i++)
                #pragma unroll
                for (int j = 0; j < NJ; j++) {
                    mma16816(acc[i][j], ahf[pb][i], bhf[pb][j]);   // hi*hi
                    mma16816(acc[i][j], ahf[pb][i], blf[pb][j]);   // hi*lo
                    mma16816(acc[i][j], alf[pb][i], bhf[pb][j]);   // lo*hi
                }
        }
        __syncthreads();
    }

    // ---------------- epilogue: bias + act + store ----------------
    const int lr  = lane >> 2;
    const int lc2 = (lane & 3) * 2;
    #pragma unroll
    for (int i = 0; i < 4; i++)
        #pragma unroll
        for (int j = 0; j < NJ; j++) {
            int col = n0 + nw + j * 8 + lc2;
            float b0 = __ldg(bias + (size_t)e * Ntot + col);
            float b1 = __ldg(bias + (size_t)e * Ntot + col + 1);
            #pragma unroll
            for (int h = 0; h < 2; h++) {
                int row = m0 + mw + i * 16 + lr + h * 8;
                float v0 = acc[i][j][2 * h + 0] + b0;
                float v1 = acc[i][j][2 * h + 1] + b1;
                if (ACT == 0) { v0 = fmaxf(v0, 0.f); v1 = fmaxf(v1, 0.f); }
                else { v0 = 1.f / (1.f + __expf(-v0)); v1 = 1.f / (1.f + __expf(-v1)); }
                size_t gi = (size_t)e * cStride + (size_t)row * ldc + col;
                if (OUTM == 0) {
                    *reinterpret_cast<float2*>(Cf + gi) = make_float2(v0, v1);
                } else {
                    bf16 h0 = __float2bfloat16(v0), h1 = __float2bfloat16(v1);
                    __nv_bfloat162 hv; hv.x = h0; hv.y = h1;
                    __nv_bfloat162 lv;
                    lv.x = __float2bfloat16(v0 - __bfloat162float(h0));
                    lv.y = __float2bfloat16(v1 - __bfloat162float(h1));
                    *reinterpret_cast<__nv_bfloat162*>(Ch + gi) = hv;
                    *reinterpret_cast<__nv_bfloat162*>(Cl + gi) = lv;
                }
            }
        }
}

// ---------------- embedding gather + split (split outputs only) ----------------
__global__ void gather_kernel(const int* __restrict__ ids, const float* __restrict__ emb) {
    int idx = blockIdx.x * blockDim.x + threadIdx.x;   // b*F + f
    if (idx >= B_ * F_) return;
    int f  = idx & (F_ - 1);
    int id = ids[idx];
    const float4* src = reinterpret_cast<const float4*>(emb + ((size_t)f * V_ + id) * DE);
    float4 v0 = src[0], v1 = src[1], v2 = src[2], v3 = src[3];

    float vals[16] = {v0.x,v0.y,v0.z,v0.w, v1.x,v1.y,v1.z,v1.w,
                      v2.x,v2.y,v2.z,v2.w, v3.x,v3.y,v3.z,v3.w};
    __align__(16) bf16 hi[16], lo[16];
    #pragma unroll
    for (int j = 0; j < 16; j++) {
        bf16 h = __float2bfloat16(vals[j]);
        hi[j] = h;
        lo[j] = __float2bfloat16(vals[j] - __bfloat162float(h));
    }
    uint4* dh = reinterpret_cast<uint4*>(g_Xh + (size_t)idx * DE);
    uint4* dl = reinterpret_cast<uint4*>(g_Xl + (size_t)idx * DE);
    dh[0] = ((uint4*)hi)[0]; dh[1] = ((uint4*)hi)[1];
    dl[0] = ((uint4*)lo)[0]; dl[1] = ((uint4*)lo)[1];
}

// ---------------- weight transpose + split: W[E,K,N] -> T[E,N,K] hi/lo ----------------
__global__ void wsplit_kernel(const float* __restrict__ W, bf16* __restrict__ Th,
                              bf16* __restrict__ Tl, int K, int N) {
    __shared__ float t[32][33];
    int e = blockIdx.z, n0 = blockIdx.x * 32, k0 = blockIdx.y * 32;
    int tx = threadIdx.x, ty = threadIdx.y;
    #pragma unroll
    for (int j = 0; j < 4; j++)
        t[ty + 8 * j][tx] = W[((size_t)e * K + k0 + ty + 8 * j) * N + n0 + tx];
    __syncthreads();
    #pragma unroll
    for (int j = 0; j < 4; j++) {
        int n = n0 + ty + 8 * j, k = k0 + tx;
        float v = t[tx][ty + 8 * j];
        bf16 h = __float2bfloat16(v);
        Th[((size_t)e * N + n) * K + k] = h;
        Tl[((size_t)e * N + n) * K + k] = __float2bfloat16(v - __bfloat162float(h));
    }
}

// ---------------- warp helpers ----------------
__device__ __forceinline__ float warp_allreduce(float v) {
    #pragma unroll
    for (int o = 16; o > 0; o >>= 1) v += __shfl_xor_sync(0xffffffffu, v, o);
    return v;
}

// ---------------- level-1 gates + combine (reads split X) ----------------
__global__ void gate1_kernel(const float* __restrict__ Wst, const float* __restrict__ bst,
                             const float* __restrict__ Wsh, const float* __restrict__ bsh)
{
    int warp = threadIdx.x >> 5, lane = threadIdx.x & 31;
    int b = blockIdx.x * 8 + warp;

    const bf16* xh = g_Xh + (size_t)b * DIN;
    const bf16* xl = g_Xl + (size_t)b * DIN;
    float xr[16];
    #pragma unroll
    for (int j = 0; j < 16; j++)
        xr[j] = __bfloat162float(xh[lane + 32 * j]) + __bfloat162float(xl[lane + 32 * j]);

    float logit[14];
    #pragma unroll
    for (int L = 0; L < 14; L++) {
        float acc = 0.f;
        if (L < 8) {
            int t = L >> 2, k = L & 3;
            const float* wc = Wst + (size_t)t * DIN * 4 + k;
            #pragma unroll
            for (int j = 0; j < 16; j++) acc += xr[j] * wc[(lane + 32 * j) * 4];
        } else {
            const float* wc = Wsh + (L - 8);
            #pragma unroll
            for (int j = 0; j < 16; j++) acc += xr[j] * wc[(lane + 32 * j) * 6];
        }
        acc = warp_allreduce(acc);
        logit[L] = acc + ((L < 8) ? bst[(L >> 2) * 4 + (L & 3)] : bsh[L - 8]);
    }

    float g0[4], g1[4], gs[6];
    {
        float m = fmaxf(fmaxf(logit[0], logit[1]), fmaxf(logit[2], logit[3]));
        float s = 0.f;
        #pragma unroll
        for (int k = 0; k < 4; k++) { g0[k] = expf(logit[k] - m); s += g0[k]; }
        #pragma unroll
        for (int k = 0; k < 4; k++) g0[k] /= s;
    }
    {
        float m = fmaxf(fmaxf(logit[4], logit[5]), fmaxf(logit[6], logit[7]));
        float s = 0.f;
        #pragma unroll
        for (int k = 0; k < 4; k++) { g1[k] = expf(logit[4 + k] - m); s += g1[k]; }
        #pragma unroll
        for (int k = 0; k < 4; k++) g1[k] /= s;
    }
    {
        float m = logit[8];
        #pragma unroll
        for (int k = 9; k < 14; k++) m = fmaxf(m, logit[k]);
        float s = 0.f;
        #pragma unroll
        for (int k = 0; k < 6; k++) { gs[k] = expf(logit[8 + k] - m); s += gs[k]; }
        #pragma unroll
        for (int k = 0; k < 6; k++) gs[k] /= s;
    }

    #pragma unroll
    for (int it = 0; it < 8; it++) {
        int c = lane + 32 * it;
        float v[6];
        #pragma unroll
        for (int e = 0; e < 6; e++) v[e] = g_O[((size_t)e * B_ + b) * H2_ + c];
        float o0 = g0[0]*v[0] + g0[1]*v[1] + g0[2]*v[4] + g0[3]*v[5];
        float o1 = g1[0]*v[2] + g1[1]*v[3] + g1[2]*v[4] + g1[3]*v[5];
        float os = 0.f;
        #pragma unroll
        for (int e = 0; e < 6; e++) os += gs[e] * v[e];
        size_t i0 = ((size_t)0 * B_ + b) * H2_ + c;
        size_t i1 = ((size_t)1 * B_ + b) * H2_ + c;
        size_t i2 = ((size_t)2 * B_ + b) * H2_ + c;
        bf16 h;
        h = __float2bfloat16(o0); g_X2h[i0] = h; g_X2l[i0] = __float2bfloat16(o0 - __bfloat162float(h));
        h = __float2bfloat16(o1); g_X2h[i1] = h; g_X2l[i1] = __float2bfloat16(o1 - __bfloat162float(h));
        h = __float2bfloat16(os); g_X2h[i2] = h; g_X2l[i2] = __float2bfloat16(os - __bfloat162float(h));
    }
}

// ---------------- level-2 gates + combine (reads split X2) ----------------
__global__ void gate2_kernel(const float* __restrict__ Wst, const float* __restrict__ bst)
{
    int warp = threadIdx.x >> 5, lane = threadIdx.x & 31;
    int b = blockIdx.x * 8 + warp;

    float x0r[8], x1r[8];
    const bf16* x0h = g_X2h + ((size_t)0 * B_ + b) * H2_;
    const bf16* x0l = g_X2l + ((size_t)0 * B_ + b) * H2_;
    const bf16* x1h = g_X2h + ((size_t)1 * B_ + b) * H2_;
    const bf16* x1l = g_X2l + ((size_t)1 * B_ + b) * H2_;
    #pragma unroll
    for (int j = 0; j < 8; j++) {
        x0r[j] = __bfloat162float(x0h[lane + 32*j]) + __bfloat162float(x0l[lane + 32*j]);
        x1r[j] = __bfloat162float(x1h[lane + 32*j]) + __bfloat162float(x1l[lane + 32*j]);
    }

    float logit[8];
    #pragma unroll
    for (int L = 0; L < 8; L++) {
        int t = L >> 2, k = L & 3;
        const float* wc = Wst + (size_t)t * H2_ * 4 + k;
        float acc = 0.f;
        if (t == 0) {
            #pragma unroll
            for (int j = 0; j < 8; j++) acc += x0r[j] * wc[(lane + 32*j) * 4];
        } else {
            #pragma unroll
            for (int j = 0; j < 8; j++) acc += x1r[j] * wc[(lane + 32*j) * 4];
        }
        acc = warp_allreduce(acc);
        logit[L] = acc + bst[t * 4 + k];
    }

    float g0[4], g1[4];
    {
        float m = fmaxf(fmaxf(logit[0], logit[1]), fmaxf(logit[2], logit[3]));
        float s = 0.f;
        #pragma unroll
        for (int k = 0; k < 4; k++) { g0[k] = expf(logit[k] - m); s += g0[k]; }
        #pragma unroll
        for (int k = 0; k < 4; k++) g0[k] /= s;
    }
    {
        float m = fmaxf(fmaxf(logit[4], logit[5]), fmaxf(logit[6], logit[7]));
        float s = 0.f;
        #pragma unroll
        for (int k = 0; k < 4; k++) { g1[k] = expf(logit[4 + k] - m); s += g1[k]; }
        #pragma unroll
        for (int k = 0; k < 4; k++) g1[k] /= s;
    }

    #pragma unroll
    for (int it = 0; it < 8; it++) {
        int c = lane + 32 * it;
        float v[6];
        #pragma unroll
        for (int e = 0; e < 6; e++) v[e] = g_O[((size_t)e * B_ + b) * H2_ + c];
        float o0 = g0[0]*v[0] + g0[1]*v[1] + g0[2]*v[4] + g0[3]*v[5];
        float o1 = g1[0]*v[2] + g1[1]*v[3] + g1[2]*v[4] + g1[3]*v[5];
        size_t i0 = ((size_t)0 * B_ + b) * H2_ + c;
        size_t i1 = ((size_t)1 * B_ + b) * H2_ + c;
        bf16 h;
        h = __float2bfloat16(o0); g_X3h[i0] = h; g_X3l[i0] = __float2bfloat16(o0 - __bfloat162float(h));
        h = __float2bfloat16(o1); g_X3h[i1] = h; g_X3l[i1] = __float2bfloat16(o1 - __bfloat162float(h));
    }
}

// ---------------- launcher ----------------
extern "C" void kernel_launch(void* const* d_in, const int* in_sizes, int n_in,
                              void* d_out, int out_size) {
    const int*   x_ids = (const int*)  d_in[0];
    const float* emb   = (const float*)d_in[1];
    const float* e1_W1 = (const float*)d_in[2];
    const float* e1_b1 = (const float*)d_in[3];
    const float* e1_W2 = (const float*)d_in[4];
    const float* e1_b2 = (const float*)d_in[5];
    const float* g1_Ws = (const float*)d_in[6];
    const float* g1_bs = (const float*)d_in[7];
    const float* g1_Wsh= (const float*)d_in[8];
    const float* g1_bsh= (const float*)d_in[9];
    const float* e2_W1 = (const float*)d_in[10];
    const float* e2_b1 = (const float*)d_in[11];
    const float* e2_W2 = (const float*)d_in[12];
    const float* e2_b2 = (const float*)d_in[13];
    const float* g2_Ws = (const float*)d_in[14];
    const float* g2_bs = (const float*)d_in[15];
    const float* tw_W1 = (const float*)d_in[16];
    const float* tw_b1 = (const float*)d_in[17];
    const float* tw_W2 = (const float*)d_in[18];
    const float* tw_b2 = (const float*)d_in[19];

    bf16 *pXh,*pXl,*pHh,*pHl,*pX2h,*pX2l,*pX3h,*pX3l,*pTh,*pTl;
    bf16 *w1h,*w1l,*w2h,*w2l,*w3h,*w3l,*w4h,*w4l,*w5h,*w5l,*w6h,*w6l;
    cudaGetSymbolAddress((void**)&pXh, g_Xh);   cudaGetSymbolAddress((void**)&pXl, g_Xl);
    cudaGetSymbolAddress((void**)&pHh, g_Hh);   cudaGetSymbolAddress((void**)&pHl, g_Hl);
    cudaGetSymbolAddress((void**)&pX2h, g_X2h); cudaGetSymbolAddress((void**)&pX2l, g_X2l);
    cudaGetSymbolAddress((void**)&pX3h, g_X3h); cudaGetSymbolAddress((void**)&pX3l, g_X3l);
    cudaGetSymbolAddress((void**)&pTh, g_Th);   cudaGetSymbolAddress((void**)&pTl, g_Tl);
    cudaGetSymbolAddress((void**)&w1h, g_w1h);  cudaGetSymbolAddress((void**)&w1l, g_w1l);
    cudaGetSymbolAddress((void**)&w2h, g_w2h);  cudaGetSymbolAddress((void**)&w2l, g_w2l);
    cudaGetSymbolAddress((void**)&w3h, g_w3h);  cudaGetSymbolAddress((void**)&w3l, g_w3l);
    cudaGetSymbolAddress((void**)&w4h, g_w4h);  cudaGetSymbolAddress((void**)&w4l, g_w4l);
    cudaGetSymbolAddress((void**)&w5h, g_w5h);  cudaGetSymbolAddress((void**)&w5l, g_w5l);
    cudaGetSymbolAddress((void**)&w6h, g_w6h);  cudaGetSymbolAddress((void**)&w6l, g_w6l);
    float *pO;
    cudaGetSymbolAddress((void**)&pO, g_O);

    const int SM128 = 2 * (2 * 128 * 128 + 2 * 128 * 128);   // 131072
    const int SM64  = 2 * (2 * 128 * 128 + 2 * 64 * 128);    //  98304
    cudaFuncSetAttribute((const void*)gemm_mma<128,0,1>, cudaFuncAttributeMaxDynamicSharedMemorySize, SM128);
    cudaFuncSetAttribute((const void*)gemm_mma<128,0,0>, cudaFuncAttributeMaxDynamicSharedMemorySize, SM128);
    cudaFuncSetAttribute((const void*)gemm_mma<64,1,0>,  cudaFuncAttributeMaxDynamicSharedMemorySize, SM64);

    dim3 tb(32, 8);
    // weight prep (transpose + bf16 split)
    wsplit_kernel<<<dim3(H1_/32, DIN/32, NE), tb>>>(e1_W1, w1h, w1l, DIN, H1_);
    wsplit_kernel<<<dim3(H2_/32, H1_/32, NE), tb>>>(e1_W2, w2h, w2l, H1_, H2_);
    wsplit_kernel<<<dim3(H1_/32, H2_/32, NE), tb>>>(e2_W1, w3h, w3l, H2_, H1_);
    wsplit_kernel<<<dim3(H2_/32, H1_/32, NE), tb>>>(e2_W2, w4h, w4l, H1_, H2_);
    wsplit_kernel<<<dim3(T1_/32, H2_/32, 2),  tb>>>(tw_W1, w5h, w5l, H2_, T1_);
    wsplit_kernel<<<dim3(T2_/32, T1_/32, 2),  tb>>>(tw_W2, w6h, w6l, T1_, T2_);

    // embedding gather + split
    gather_kernel<<<(B_ * F_) / 256, 256>>>(x_ids, emb);

    // L1 experts stage 1: relu(X @ W1) -> H hi/lo   (shared A)
    gemm_mma<128,0,1><<<dim3(H1_/128, B_/128, NE), 256, SM128>>>(
        pXh, pXl, w1h, w1l, e1_b1, nullptr, pHh, pHl,
        DIN, H1_, 0, 0, (size_t)B_*H1_, H1_);
    // L1 experts stage 2: relu(H @ W2) -> O fp32
    gemm_mma<128,0,0><<<dim3(H2_/128, B_/128, NE), 256, SM128>>>(
        pHh, pHl, w2h, w2l, e1_b2, pO, nullptr, nullptr,
        H1_, H2_, 2, (size_t)B_*H1_, (size_t)B_*H2_, H2_);
    // L1 gates + combine -> X2 hi/lo
    gate1_kernel<<<B_/8, 256>>>(g1_Ws, g1_bs, g1_Wsh, g1_bsh);

    // L2 experts stage 1: relu(X2[e/2] @ W1) -> H hi/lo
    gemm_mma<128,0,1><<<dim3(H1_/128, B_/128, NE), 256, SM128>>>(
        pX2h, pX2l, w3h, w3l, e2_b1, nullptr, pHh, pHl,
        H2_, H1_, 1, (size_t)B_*H2_, (size_t)B_*H1_, H1_);
    // L2 experts stage 2: relu(H @ W2) -> O fp32
    gemm_mma<128,0,0><<<dim3(H2_/128, B_/128, NE), 256, SM128>>>(
        pHh, pHl, w4h, w4l, e2_b2, pO, nullptr, nullptr,
        H1_, H2_, 2, (size_t)B_*H1_, (size_t)B_*H2_, H2_);
    // L2 gates + combine -> X3 hi/lo
    gate2_kernel<<<B_/8, 256>>>(g2_Ws, g2_bs);

    // tower stage 1: relu(X3[t] @ tw_W1) -> T hi/lo
    gemm_mma<128,0,1><<<dim3(T1_/128, B_/128, 2), 256, SM128>>>(
        pX3h, pX3l, w5h, w5l, tw_b1, nullptr, pTh, pTl,
        H2_, T1_, 2, (size_t)B_*H2_, (size_t)B_*T1_, T1_);
    // tower stage 2: sigmoid(T @ tw_W2) -> d_out [B, 2*64]
    gemm_mma<64,1,0><<<dim3(T2_/64, B_/128, 2), 256, SM64>>>(
        pTh, pTl, w6h, w6l, tw_b2, (float*)d_out, nullptr, nullptr,
        T1_, T2_, 2, (size_t)B_*T1_, (size_t)T2_, 2*T2_);
}

// round 5
// speedup vs baseline: 3.4976x; 1.4266x over previous
#include <cuda_runtime.h>
#include <cuda_fp16.h>
#include <math.h>
#include <stdint.h>

typedef __half f16;

#define B_   16384
#define F_   32
#define V_   50000
#define DE   16
#define DIN  512
#define NE   6
#define H1_  512
#define H2_  256
#define T1_  128
#define T2_  64

// ---------------- scratch (device globals; no runtime alloc) ----------------
__device__ __align__(256) f16   g_Xf [(size_t)B_*DIN];      // activations, single fp16
__device__ __align__(256) f16   g_Hf [(size_t)NE*B_*H1_];
__device__ __align__(256) float g_O  [(size_t)NE*B_*H2_];   // expert outputs fp32 (gates read)
__device__ __align__(256) f16   g_X2f[(size_t)3*B_*H2_];
__device__ __align__(256) f16   g_X3f[(size_t)2*B_*H2_];
__device__ __align__(256) f16   g_Tf [(size_t)2*B_*T1_];
// transposed split weights, layout [E, N, K] (K-major rows), fp16 hi/lo
__device__ __align__(256) f16 g_w1h[(size_t)NE*H1_*DIN], g_w1l[(size_t)NE*H1_*DIN];
__device__ __align__(256) f16 g_w2h[(size_t)NE*H2_*H1_], g_w2l[(size_t)NE*H2_*H1_];
__device__ __align__(256) f16 g_w3h[(size_t)NE*H1_*H2_], g_w3l[(size_t)NE*H1_*H2_];
__device__ __align__(256) f16 g_w4h[(size_t)NE*H2_*H1_], g_w4l[(size_t)NE*H2_*H1_];
__device__ __align__(256) f16 g_w5h[(size_t)2*T1_*H2_], g_w5l[(size_t)2*T1_*H2_];
__device__ __align__(256) f16 g_w6h[(size_t)2*T2_*T1_], g_w6l[(size_t)2*T2_*T1_];

// ---------------- helpers ----------------
__device__ __forceinline__ uint32_t smem_u32(const void* p) {
    uint32_t a;
    asm("{ .reg .u64 t; cvta.to.shared.u64 t, %1; cvt.u32.u64 %0, t; }" : "=r"(a) : "l"(p));
    return a;
}
__device__ __forceinline__ void cp16(uint32_t dst, const void* src) {
    asm volatile("cp.async.cg.shared.global [%0], [%1], 16;" :: "r"(dst), "l"(src));
}
__device__ __forceinline__ void ldsm4(uint32_t* r, uint32_t a) {
    asm volatile("ldmatrix.sync.aligned.m8n8.x4.shared.b16 {%0,%1,%2,%3}, [%4];"
                 : "=r"(r[0]), "=r"(r[1]), "=r"(r[2]), "=r"(r[3]) : "r"(a));
}
__device__ __forceinline__ void mma16816(float* c, const uint32_t* a, const uint32_t* b) {
    asm volatile("mma.sync.aligned.m16n8k16.row.col.f32.f16.f16.f32 "
                 "{%0,%1,%2,%3}, {%4,%5,%6,%7}, {%8,%9}, {%0,%1,%2,%3};"
                 : "+f"(c[0]), "+f"(c[1]), "+f"(c[2]), "+f"(c[3])
                 : "r"(a[0]), "r"(a[1]), "r"(a[2]), "r"(a[3]), "r"(b[0]), "r"(b[1]));
}
__device__ __forceinline__ uint32_t swz(uint32_t off) { return off ^ ((off >> 3) & 0x70); }

// ---------------- fp16 2-product split GEMM ----------------
// C[e] = act(A[aidx] @ (Bh[e] + Bl[e])^T + bias[e])
// A: [*, K] fp16 row-major; B: [E, Ntot, K] fp16 hi/lo (K-major rows)
// NT: CTA N-tile (128 or 64). ACT: 0=relu 1=sigmoid. OUTM: 0=f32, 1=f16.
template<int NT, int ACT, int OUTM>
__global__ void __launch_bounds__(256, 1)
gemm_mma(const f16* __restrict__ A,
         const f16* __restrict__ Bh, const f16* __restrict__ Bl,
         const float* __restrict__ bias,
         float* __restrict__ Cf, f16* __restrict__ Ch,
         int K, int Ntot, int a_sel, size_t aStride, size_t cStride, int ldc)
{
    extern __shared__ char smem_raw[];
    constexpr int ASTG  = 128 * 128;            // A tile: 128 rows x 128B (64 fp16)
    constexpr int BSTG  = NT * 128;
    constexpr int STAGE = ASTG + 2 * BSTG;
    constexpr int NJ    = NT / 32;              // n8 tiles per warp

    const int tid  = threadIdx.x;
    const int wid  = tid >> 5;
    const int lane = tid & 31;
    const int e  = blockIdx.z;
    const int m0 = blockIdx.y * 128;
    const int n0 = blockIdx.x * NT;

    const int aidx = (a_sel == 0) ? 0 : ((a_sel == 1) ? (e >> 1) : e);
    const f16* pA  = A  + (size_t)aidx * aStride + (size_t)m0 * K;
    const f16* pBh = Bh + ((size_t)e * Ntot + n0) * K;
    const f16* pBl = Bl + ((size_t)e * Ntot + n0) * K;

    const uint32_t sb = smem_u32(smem_raw);

    // warp tiling: 2 x 4 warp grid; warp tile 64 x (NT/4)
    const int wm = wid >> 2, wn = wid & 3;
    const int mw = wm * 64;
    const int nw = wn * (NT / 4);

    float acc[4][NJ][4];
    #pragma unroll
    for (int i = 0; i < 4; i++)
        #pragma unroll
        for (int j = 0; j < NJ; j++)
            #pragma unroll
            for (int q = 0; q < 4; q++) acc[i][j][q] = 0.f;

    auto load_stage = [&](int kt, int st) {
        const uint32_t base = sb + st * STAGE;
        const int k0 = kt * 64;
        #pragma unroll
        for (int t = 0; t < 4; t++) {                 // A: 128 rows x 8 chunks / 256 thr
            int id = tid + t * 256;
            int r = id >> 3, q = id & 7;
            uint32_t off = swz((uint32_t)(r * 128 + q * 16));
            cp16(base + off, pA + (size_t)r * K + k0 + q * 8);
        }
        #pragma unroll
        for (int t = 0; t < NT / 32; t++) {           // B hi+lo: NT rows x 8 chunks / 256 thr
            int id = tid + t * 256;
            int r = id >> 3, q = id & 7;
            uint32_t off = swz((uint32_t)(r * 128 + q * 16));
            cp16(base + ASTG + off,        pBh + (size_t)r * K + k0 + q * 8);
            cp16(base + ASTG + BSTG + off, pBl + (size_t)r * K + k0 + q * 8);
        }
        asm volatile("cp.async.commit_group;" ::: "memory");
    };

    load_stage(0, 0);
    const int T = K >> 6;
    for (int kt = 0; kt < T; kt++) {
        if (kt + 1 < T) {
            load_stage(kt + 1, (kt + 1) & 1);
            asm volatile("cp.async.wait_group 1;" ::: "memory");
        } else {
            asm volatile("cp.async.wait_group 0;" ::: "memory");
        }
        __syncthreads();

        const uint32_t abase = sb + (kt & 1) * STAGE;
        const uint32_t bbase = abase + ASTG;

        #pragma unroll
        for (int ks = 0; ks < 4; ks++) {
            const int cb = ks * 32 + (lane >> 4) * 16;
            uint32_t af[4][4];
            #pragma unroll
            for (int i = 0; i < 4; i++) {
                int row = mw + i * 16 + (lane & 15);
                ldsm4(af[i], abase + swz((uint32_t)(row * 128 + cb)));
            }
            uint32_t bhf[NJ][2], blf[NJ][2];
            #pragma unroll
            for (int bb = 0; bb < NT / 64; bb++) {
                int row = nw + bb * 16 + (lane & 15);
                uint32_t off = swz((uint32_t)(row * 128 + cb));
                uint32_t tr[4];
                ldsm4(tr, bbase + off);
                bhf[2*bb][0] = tr[0]; bhf[2*bb+1][0] = tr[1];
                bhf[2*bb][1] = tr[2]; bhf[2*bb+1][1] = tr[3];
                ldsm4(tr, bbase + BSTG + off);
                blf[2*bb][0] = tr[0]; blf[2*bb+1][0] = tr[1];
                blf[2*bb][1] = tr[2]; blf[2*bb+1][1] = tr[3];
            }
            #pragma unroll
            for (int i = 0; i < 4; i++)
                #pragma unroll
                for (int j = 0; j < NJ; j++) {
                    mma16816(acc[i][j], af[i], bhf[j]);   // A * B_hi
                    mma16816(acc[i][j], af[i], blf[j]);   // A * B_lo
                }
        }
        __syncthreads();
    }

    // ---------------- epilogue: bias + act + store ----------------
    const int lr  = lane >> 2;
    const int lc2 = (lane & 3) * 2;
    #pragma unroll
    for (int i = 0; i < 4; i++)
        #pragma unroll
        for (int j = 0; j < NJ; j++) {
            int col = n0 + nw + j * 8 + lc2;
            float b0 = __ldg(bias + (size_t)e * Ntot + col);
            float b1 = __ldg(bias + (size_t)e * Ntot + col + 1);
            #pragma unroll
            for (int h = 0; h < 2; h++) {
                int row = m0 + mw + i * 16 + lr + h * 8;
                float v0 = acc[i][j][2 * h + 0] + b0;
                float v1 = acc[i][j][2 * h + 1] + b1;
                if (ACT == 0) { v0 = fmaxf(v0, 0.f); v1 = fmaxf(v1, 0.f); }
                else { v0 = 1.f / (1.f + __expf(-v0)); v1 = 1.f / (1.f + __expf(-v1)); }
                size_t gi = (size_t)e * cStride + (size_t)row * ldc + col;
                if (OUTM == 0) {
                    *reinterpret_cast<float2*>(Cf + gi) = make_float2(v0, v1);
                } else {
                    __half2 hv = __floats2half2_rn(v0, v1);
                    *reinterpret_cast<__half2*>(Ch + gi) = hv;
                }
            }
        }
}

// ---------------- embedding gather -> fp16 ----------------
__global__ void gather_kernel(const int* __restrict__ ids, const float* __restrict__ emb) {
    int idx = blockIdx.x * blockDim.x + threadIdx.x;   // b*F + f
    if (idx >= B_ * F_) return;
    int f  = idx & (F_ - 1);
    int id = ids[idx];
    const float4* src = reinterpret_cast<const float4*>(emb + ((size_t)f * V_ + id) * DE);
    float4 v0 = src[0], v1 = src[1], v2 = src[2], v3 = src[3];

    __align__(16) f16 hv[16];
    float vals[16] = {v0.x,v0.y,v0.z,v0.w, v1.x,v1.y,v1.z,v1.w,
                      v2.x,v2.y,v2.z,v2.w, v3.x,v3.y,v3.z,v3.w};
    #pragma unroll
    for (int j = 0; j < 16; j++) hv[j] = __float2half_rn(vals[j]);
    uint4* dh = reinterpret_cast<uint4*>(g_Xf + (size_t)idx * DE);
    dh[0] = ((uint4*)hv)[0]; dh[1] = ((uint4*)hv)[1];
}

// ---------------- weight transpose + fp16 split: W[E,K,N] -> T[E,N,K] hi/lo ----------------
__global__ void wsplit_kernel(const float* __restrict__ W, f16* __restrict__ Th,
                              f16* __restrict__ Tl, int K, int N) {
    __shared__ float t[32][33];
    int e = blockIdx.z, n0 = blockIdx.x * 32, k0 = blockIdx.y * 32;
    int tx = threadIdx.x, ty = threadIdx.y;
    #pragma unroll
    for (int j = 0; j < 4; j++)
        t[ty + 8 * j][tx] = W[((size_t)e * K + k0 + ty + 8 * j) * N + n0 + tx];
    __syncthreads();
    #pragma unroll
    for (int j = 0; j < 4; j++) {
        int n = n0 + ty + 8 * j, k = k0 + tx;
        float v = t[tx][ty + 8 * j];
        f16 h = __float2half_rn(v);
        Th[((size_t)e * N + n) * K + k] = h;
        Tl[((size_t)e * N + n) * K + k] = __float2half_rn(v - __half2float(h));
    }
}

// ---------------- warp helpers ----------------
__device__ __forceinline__ float warp_allreduce(float v) {
    #pragma unroll
    for (int o = 16; o > 0; o >>= 1) v += __shfl_xor_sync(0xffffffffu, v, o);
    return v;
}

// ---------------- level-1 gates + combine ----------------
__global__ void gate1_kernel(const float* __restrict__ Wst, const float* __restrict__ bst,
                             const float* __restrict__ Wsh, const float* __restrict__ bsh)
{
    int warp = threadIdx.x >> 5, lane = threadIdx.x & 31;
    int b = blockIdx.x * 8 + warp;

    const f16* x = g_Xf + (size_t)b * DIN;
    float xr[16];
    #pragma unroll
    for (int j = 0; j < 16; j++) xr[j] = __half2float(x[lane + 32 * j]);

    float logit[14];
    #pragma unroll
    for (int L = 0; L < 14; L++) {
        float acc = 0.f;
        if (L < 8) {
            int t = L >> 2, k = L & 3;
            const float* wc = Wst + (size_t)t * DIN * 4 + k;
            #pragma unroll
            for (int j = 0; j < 16; j++) acc += xr[j] * wc[(lane + 32 * j) * 4];
        } else {
            const float* wc = Wsh + (L - 8);
            #pragma unroll
            for (int j = 0; j < 16; j++) acc += xr[j] * wc[(lane + 32 * j) * 6];
        }
        acc = warp_allreduce(acc);
        logit[L] = acc + ((L < 8) ? bst[(L >> 2) * 4 + (L & 3)] : bsh[L - 8]);
    }

    float g0[4], g1[4], gs[6];
    {
        float m = fmaxf(fmaxf(logit[0], logit[1]), fmaxf(logit[2], logit[3]));
        float s = 0.f;
        #pragma unroll
        for (int k = 0; k < 4; k++) { g0[k] = expf(logit[k] - m); s += g0[k]; }
        #pragma unroll
        for (int k = 0; k < 4; k++) g0[k] /= s;
    }
    {
        float m = fmaxf(fmaxf(logit[4], logit[5]), fmaxf(logit[6], logit[7]));
        float s = 0.f;
        #pragma unroll
        for (int k = 0; k < 4; k++) { g1[k] = expf(logit[4 + k] - m); s += g1[k]; }
        #pragma unroll
        for (int k = 0; k < 4; k++) g1[k] /= s;
    }
    {
        float m = logit[8];
        #pragma unroll
        for (int k = 9; k < 14; k++) m = fmaxf(m, logit[k]);
        float s = 0.f;
        #pragma unroll
        for (int k = 0; k < 6; k++) { gs[k] = expf(logit[8 + k] - m); s += gs[k]; }
        #pragma unroll
        for (int k = 0; k < 6; k++) gs[k] /= s;
    }

    #pragma unroll
    for (int it = 0; it < 8; it++) {
        int c = lane + 32 * it;
        float v[6];
        #pragma unroll
        for (int e = 0; e < 6; e++) v[e] = g_O[((size_t)e * B_ + b) * H2_ + c];
        float o0 = g0[0]*v[0] + g0[1]*v[1] + g0[2]*v[4] + g0[3]*v[5];
        float o1 = g1[0]*v[2] + g1[1]*v[3] + g1[2]*v[4] + g1[3]*v[5];
        float os = 0.f;
        #pragma unroll
        for (int e = 0; e < 6; e++) os += gs[e] * v[e];
        g_X2f[((size_t)0 * B_ + b) * H2_ + c] = __float2half_rn(o0);
        g_X2f[((size_t)1 * B_ + b) * H2_ + c] = __float2half_rn(o1);
        g_X2f[((size_t)2 * B_ + b) * H2_ + c] = __float2half_rn(os);
    }
}

// ---------------- level-2 gates + combine ----------------
__global__ void gate2_kernel(const float* __restrict__ Wst, const float* __restrict__ bst)
{
    int warp = threadIdx.x >> 5, lane = threadIdx.x & 31;
    int b = blockIdx.x * 8 + warp;

    float x0r[8], x1r[8];
    const f16* x0 = g_X2f + ((size_t)0 * B_ + b) * H2_;
    const f16* x1 = g_X2f + ((size_t)1 * B_ + b) * H2_;
    #pragma unroll
    for (int j = 0; j < 8; j++) {
        x0r[j] = __half2float(x0[lane + 32*j]);
        x1r[j] = __half2float(x1[lane + 32*j]);
    }

    float logit[8];
    #pragma unroll
    for (int L = 0; L < 8; L++) {
        int t = L >> 2, k = L & 3;
        const float* wc = Wst + (size_t)t * H2_ * 4 + k;
        float acc = 0.f;
        if (t == 0) {
            #pragma unroll
            for (int j = 0; j < 8; j++) acc += x0r[j] * wc[(lane + 32*j) * 4];
        } else {
            #pragma unroll
            for (int j = 0; j < 8; j++) acc += x1r[j] * wc[(lane + 32*j) * 4];
        }
        acc = warp_allreduce(acc);
        logit[L] = acc + bst[t * 4 + k];
    }

    float g0[4], g1[4];
    {
        float m = fmaxf(fmaxf(logit[0], logit[1]), fmaxf(logit[2], logit[3]));
        float s = 0.f;
        #pragma unroll
        for (int k = 0; k < 4; k++) { g0[k] = expf(logit[k] - m); s += g0[k]; }
        #pragma unroll
        for (int k = 0; k < 4; k++) g0[k] /= s;
    }
    {
        float m = fmaxf(fmaxf(logit[4], logit[5]), fmaxf(logit[6], logit[7]));
        float s = 0.f;
        #pragma unroll
        for (int k = 0; k < 4; k++) { g1[k] = expf(logit[4 + k] - m); s += g1[k]; }
        #pragma unroll
        for (int k = 0; k < 4; k++) g1[k] /= s;
    }

    #pragma unroll
    for (int it = 0; it < 8; it++) {
        int c = lane + 32 * it;
        float v[6];
        #pragma unroll
        for (int e = 0; e < 6; e++) v[e] = g_O[((size_t)e * B_ + b) * H2_ + c];
        float o0 = g0[0]*v[0] + g0[1]*v[1] + g0[2]*v[4] + g0[3]*v[5];
        float o1 = g1[0]*v[2] + g1[1]*v[3] + g1[2]*v[4] + g1[3]*v[5];
        g_X3f[((size_t)0 * B_ + b) * H2_ + c] = __float2half_rn(o0);
        g_X3f[((size_t)1 * B_ + b) * H2_ + c] = __float2half_rn(o1);
    }
}

// ---------------- launcher ----------------
extern "C" void kernel_launch(void* const* d_in, const int* in_sizes, int n_in,
                              void* d_out, int out_size) {
    const int*   x_ids = (const int*)  d_in[0];
    const float* emb   = (const float*)d_in[1];
    const float* e1_W1 = (const float*)d_in[2];
    const float* e1_b1 = (const float*)d_in[3];
    const float* e1_W2 = (const float*)d_in[4];
    const float* e1_b2 = (const float*)d_in[5];
    const float* g1_Ws = (const float*)d_in[6];
    const float* g1_bs = (const float*)d_in[7];
    const float* g1_Wsh= (const float*)d_in[8];
    const float* g1_bsh= (const float*)d_in[9];
    const float* e2_W1 = (const float*)d_in[10];
    const float* e2_b1 = (const float*)d_in[11];
    const float* e2_W2 = (const float*)d_in[12];
    const float* e2_b2 = (const float*)d_in[13];
    const float* g2_Ws = (const float*)d_in[14];
    const float* g2_bs = (const float*)d_in[15];
    const float* tw_W1 = (const float*)d_in[16];
    const float* tw_b1 = (const float*)d_in[17];
    const float* tw_W2 = (const float*)d_in[18];
    const float* tw_b2 = (const float*)d_in[19];

    f16 *pXf,*pHf,*pX2f,*pX3f,*pTf;
    f16 *w1h,*w1l,*w2h,*w2l,*w3h,*w3l,*w4h,*w4l,*w5h,*w5l,*w6h,*w6l;
    cudaGetSymbolAddress((void**)&pXf,  g_Xf);
    cudaGetSymbolAddress((void**)&pHf,  g_Hf);
    cudaGetSymbolAddress((void**)&pX2f, g_X2f);
    cudaGetSymbolAddress((void**)&pX3f, g_X3f);
    cudaGetSymbolAddress((void**)&pTf,  g_Tf);
    cudaGetSymbolAddress((void**)&w1h, g_w1h);  cudaGetSymbolAddress((void**)&w1l, g_w1l);
    cudaGetSymbolAddress((void**)&w2h, g_w2h);  cudaGetSymbolAddress((void**)&w2l, g_w2l);
    cudaGetSymbolAddress((void**)&w3h, g_w3h);  cudaGetSymbolAddress((void**)&w3l, g_w3l);
    cudaGetSymbolAddress((void**)&w4h, g_w4h);  cudaGetSymbolAddress((void**)&w4l, g_w4l);
    cudaGetSymbolAddress((void**)&w5h, g_w5h);  cudaGetSymbolAddress((void**)&w5l, g_w5l);
    cudaGetSymbolAddress((void**)&w6h, g_w6h);  cudaGetSymbolAddress((void**)&w6l, g_w6l);
    float *pO;
    cudaGetSymbolAddress((void**)&pO, g_O);

    const int SM128 = 2 * (128 * 128 + 2 * 128 * 128);   // 98304
    const int SM64  = 2 * (128 * 128 + 2 * 64 * 128);    // 65536
    cudaFuncSetAttribute((const void*)gemm_mma<128,0,1>, cudaFuncAttributeMaxDynamicSharedMemorySize, SM128);
    cudaFuncSetAttribute((const void*)gemm_mma<128,0,0>, cudaFuncAttributeMaxDynamicSharedMemorySize, SM128);
    cudaFuncSetAttribute((const void*)gemm_mma<64,1,0>,  cudaFuncAttributeMaxDynamicSharedMemorySize, SM64);

    dim3 tb(32, 8);
    // weight prep (transpose + fp16 split)
    wsplit_kernel<<<dim3(H1_/32, DIN/32, NE), tb>>>(e1_W1, w1h, w1l, DIN, H1_);
    wsplit_kernel<<<dim3(H2_/32, H1_/32, NE), tb>>>(e1_W2, w2h, w2l, H1_, H2_);
    wsplit_kernel<<<dim3(H1_/32, H2_/32, NE), tb>>>(e2_W1, w3h, w3l, H2_, H1_);
    wsplit_kernel<<<dim3(H2_/32, H1_/32, NE), tb>>>(e2_W2, w4h, w4l, H1_, H2_);
    wsplit_kernel<<<dim3(T1_/32, H2_/32, 2),  tb>>>(tw_W1, w5h, w5l, H2_, T1_);
    wsplit_kernel<<<dim3(T2_/32, T1_/32, 2),  tb>>>(tw_W2, w6h, w6l, T1_, T2_);

    // embedding gather -> fp16
    gather_kernel<<<(B_ * F_) / 256, 256>>>(x_ids, emb);

    // L1 experts stage 1: relu(X @ W1) -> H fp16   (shared A)
    gemm_mma<128,0,1><<<dim3(H1_/128, B_/128, NE), 256, SM128>>>(
        pXf, w1h, w1l, e1_b1, nullptr, pHf,
        DIN, H1_, 0, 0, (size_t)B_*H1_, H1_);
    // L1 experts stage 2: relu(H @ W2) -> O fp32
    gemm_mma<128,0,0><<<dim3(H2_/128, B_/128, NE), 256, SM128>>>(
        pHf, w2h, w2l, e1_b2, pO, nullptr,
        H1_, H2_, 2, (size_t)B_*H1_, (size_t)B_*H2_, H2_);
    // L1 gates + combine -> X2 fp16
    gate1_kernel<<<B_/8, 256>>>(g1_Ws, g1_bs, g1_Wsh, g1_bsh);

    // L2 experts stage 1: relu(X2[e/2] @ W1) -> H fp16
    gemm_mma<128,0,1><<<dim3(H1_/128, B_/128, NE), 256, SM128>>>(
        pX2f, w3h, w3l, e2_b1, nullptr, pHf,
        H2_, H1_, 1, (size_t)B_*H2_, (size_t)B_*H1_, H1_);
    // L2 experts stage 2: relu(H @ W2) -> O fp32
    gemm_mma<128,0,0><<<dim3(H2_/128, B_/128, NE), 256, SM128>>>(
        pHf, w4h, w4l, e2_b2, pO, nullptr,
        H1_, H2_, 2, (size_t)B_*H1_, (size_t)B_*H2_, H2_);
    // L2 gates + combine -> X3 fp16
    gate2_kernel<<<B_/8, 256>>>(g2_Ws, g2_bs);

    // tower stage 1: relu(X3[t] @ tw_W1) -> T fp16
    gemm_mma<128,0,1><<<dim3(T1_/128, B_/128, 2), 256, SM128>>>(
        pX3f, w5h, w5l, tw_b1, nullptr, pTf,
        H2_, T1_, 2, (size_t)B_*H2_, (size_t)B_*T1_, T1_);
    // tower stage 2: sigmoid(T @ tw_W2) -> d_out [B, 2*64]
    gemm_mma<64,1,0><<<dim3(T2_/64, B_/128, 2), 256, SM64>>>(
        pTf, w6h, w6l, tw_b2, (float*)d_out, nullptr,
        T1_, T2_, 2, (size_t)B_*T1_, (size_t)T2_, 2*T2_);
}

// round 6
// speedup vs baseline: 5.2849x; 1.5110x over previous
#include <cuda_runtime.h>
#include <cuda_fp16.h>
#include <math.h>
#include <stdint.h>

typedef __half f16;

#define B_   16384
#define F_   32
#define V_   50000
#define DE   16
#define DIN  512
#define NE   6
#define H1_  512
#define H2_  256
#define T1_  128
#define T2_  64

// ---------------- scratch (device globals; no runtime alloc) ----------------
__device__ __align__(256) f16 g_Xf [(size_t)B_*DIN];      // activations fp16
__device__ __align__(256) f16 g_Hf [(size_t)NE*B_*H1_];
__device__ __align__(256) f16 g_O  [(size_t)NE*B_*H2_];   // expert outputs fp16
__device__ __align__(256) f16 g_X2f[(size_t)3*B_*H2_];
__device__ __align__(256) f16 g_X3f[(size_t)2*B_*H2_];
__device__ __align__(256) f16 g_Tf [(size_t)2*B_*T1_];
// transposed fp16 weights, layout [E, N, K] (K-major rows)
__device__ __align__(256) f16 g_w1[(size_t)NE*H1_*DIN];
__device__ __align__(256) f16 g_w2[(size_t)NE*H2_*H1_];
__device__ __align__(256) f16 g_w3[(size_t)NE*H1_*H2_];
__device__ __align__(256) f16 g_w4[(size_t)NE*H2_*H1_];
__device__ __align__(256) f16 g_w5[(size_t)2*T1_*H2_];
__device__ __align__(256) f16 g_w6[(size_t)2*T2_*T1_];

// ---------------- helpers ----------------
__device__ __forceinline__ uint32_t smem_u32(const void* p) {
    uint32_t a;
    asm("{ .reg .u64 t; cvta.to.shared.u64 t, %1; cvt.u32.u64 %0, t; }" : "=r"(a) : "l"(p));
    return a;
}
__device__ __forceinline__ void cp16(uint32_t dst, const void* src) {
    asm volatile("cp.async.cg.shared.global [%0], [%1], 16;" :: "r"(dst), "l"(src));
}
__device__ __forceinline__ void ldsm4(uint32_t* r, uint32_t a) {
    asm volatile("ldmatrix.sync.aligned.m8n8.x4.shared.b16 {%0,%1,%2,%3}, [%4];"
                 : "=r"(r[0]), "=r"(r[1]), "=r"(r[2]), "=r"(r[3]) : "r"(a));
}
__device__ __forceinline__ void mma16816(float* c, const uint32_t* a, const uint32_t* b) {
    asm volatile("mma.sync.aligned.m16n8k16.row.col.f32.f16.f16.f32 "
                 "{%0,%1,%2,%3}, {%4,%5,%6,%7}, {%8,%9}, {%0,%1,%2,%3};"
                 : "+f"(c[0]), "+f"(c[1]), "+f"(c[2]), "+f"(c[3])
                 : "r"(a[0]), "r"(a[1]), "r"(a[2]), "r"(a[3]), "r"(b[0]), "r"(b[1]));
}
__device__ __forceinline__ uint32_t swz(uint32_t off) { return off ^ ((off >> 3) & 0x70); }

// ---------------- fp16 grouped GEMM ----------------
// C[e] = act(A[aidx] @ B[e]^T + bias[e])
// A: [*, K] fp16 row-major; B: [E, Ntot, K] fp16 (K-major rows)
// NT: CTA N-tile (128 or 64). ACT: 0=relu 1=sigmoid. OUTM: 0=f32, 1=f16.
template<int NT, int ACT, int OUTM>
__global__ void __launch_bounds__(256, 1)
gemm_mma(const f16* __restrict__ A, const f16* __restrict__ B,
         const float* __restrict__ bias,
         float* __restrict__ Cf, f16* __restrict__ Ch,
         int K, int Ntot, int a_sel, size_t aStride, size_t cStride, int ldc)
{
    extern __shared__ char smem_raw[];
    constexpr int ASTG  = 128 * 128;            // A tile: 128 rows x 128B (64 fp16)
    constexpr int BSTG  = NT * 128;
    constexpr int STAGE = ASTG + BSTG;
    constexpr int NJ    = NT / 32;              // n8 tiles per warp

    const int tid  = threadIdx.x;
    const int wid  = tid >> 5;
    const int lane = tid & 31;
    const int e  = blockIdx.z;
    const int m0 = blockIdx.y * 128;
    const int n0 = blockIdx.x * NT;

    const int aidx = (a_sel == 0) ? 0 : ((a_sel == 1) ? (e >> 1) : e);
    const f16* pA = A + (size_t)aidx * aStride + (size_t)m0 * K;
    const f16* pB = B + ((size_t)e * Ntot + n0) * K;

    const uint32_t sb = smem_u32(smem_raw);

    // warp tiling: 2 x 4 warp grid; warp tile 64 x (NT/4)
    const int wm = wid >> 2, wn = wid & 3;
    const int mw = wm * 64;
    const int nw = wn * (NT / 4);

    float acc[4][NJ][4];
    #pragma unroll
    for (int i = 0; i < 4; i++)
        #pragma unroll
        for (int j = 0; j < NJ; j++)
            #pragma unroll
            for (int q = 0; q < 4; q++) acc[i][j][q] = 0.f;

    auto load_stage = [&](int kt, int st) {
        const uint32_t base = sb + st * STAGE;
        const int k0 = kt * 64;
        #pragma unroll
        for (int t = 0; t < 4; t++) {                 // A: 128 rows x 8 chunks / 256 thr
            int id = tid + t * 256;
            int r = id >> 3, q = id & 7;
            uint32_t off = swz((uint32_t)(r * 128 + q * 16));
            cp16(base + off, pA + (size_t)r * K + k0 + q * 8);
        }
        #pragma unroll
        for (int t = 0; t < NT / 32; t++) {           // B: NT rows x 8 chunks / 256 thr
            int id = tid + t * 256;
            int r = id >> 3, q = id & 7;
            uint32_t off = swz((uint32_t)(r * 128 + q * 16));
            cp16(base + ASTG + off, pB + (size_t)r * K + k0 + q * 8);
        }
        asm volatile("cp.async.commit_group;" ::: "memory");
    };

    load_stage(0, 0);
    const int T = K >> 6;
    for (int kt = 0; kt < T; kt++) {
        if (kt + 1 < T) {
            load_stage(kt + 1, (kt + 1) & 1);
            asm volatile("cp.async.wait_group 1;" ::: "memory");
        } else {
            asm volatile("cp.async.wait_group 0;" ::: "memory");
        }
        __syncthreads();

        const uint32_t abase = sb + (kt & 1) * STAGE;
        const uint32_t bbase = abase + ASTG;

        #pragma unroll
        for (int ks = 0; ks < 4; ks++) {
            const int cb = ks * 32 + (lane >> 4) * 16;
            uint32_t af[4][4];
            #pragma unroll
            for (int i = 0; i < 4; i++) {
                int row = mw + i * 16 + (lane & 15);
                ldsm4(af[i], abase + swz((uint32_t)(row * 128 + cb)));
            }
            uint32_t bf[NJ][2];
            #pragma unroll
            for (int bb = 0; bb < NT / 64; bb++) {
                int row = nw + bb * 16 + (lane & 15);
                uint32_t tr[4];
                ldsm4(tr, bbase + swz((uint32_t)(row * 128 + cb)));
                bf[2*bb][0] = tr[0]; bf[2*bb+1][0] = tr[1];
                bf[2*bb][1] = tr[2]; bf[2*bb+1][1] = tr[3];
            }
            #pragma unroll
            for (int i = 0; i < 4; i++)
                #pragma unroll
                for (int j = 0; j < NJ; j++)
                    mma16816(acc[i][j], af[i], bf[j]);
        }
        __syncthreads();
    }

    // ---------------- epilogue: bias + act + store ----------------
    const int lr  = lane >> 2;
    const int lc2 = (lane & 3) * 2;
    #pragma unroll
    for (int i = 0; i < 4; i++)
        #pragma unroll
        for (int j = 0; j < NJ; j++) {
            int col = n0 + nw + j * 8 + lc2;
            float b0 = __ldg(bias + (size_t)e * Ntot + col);
            float b1 = __ldg(bias + (size_t)e * Ntot + col + 1);
            #pragma unroll
            for (int h = 0; h < 2; h++) {
                int row = m0 + mw + i * 16 + lr + h * 8;
                float v0 = acc[i][j][2 * h + 0] + b0;
                float v1 = acc[i][j][2 * h + 1] + b1;
                if (ACT == 0) { v0 = fmaxf(v0, 0.f); v1 = fmaxf(v1, 0.f); }
                else { v0 = 1.f / (1.f + __expf(-v0)); v1 = 1.f / (1.f + __expf(-v1)); }
                size_t gi = (size_t)e * cStride + (size_t)row * ldc + col;
                if (OUTM == 0) {
                    *reinterpret_cast<float2*>(Cf + gi) = make_float2(v0, v1);
                } else {
                    *reinterpret_cast<__half2*>(Ch + gi) = __floats2half2_rn(v0, v1);
                }
            }
        }
}

// ---------------- embedding gather -> fp16 ----------------
__global__ void gather_kernel(const int* __restrict__ ids, const float* __restrict__ emb) {
    int idx = blockIdx.x * blockDim.x + threadIdx.x;   // b*F + f
    if (idx >= B_ * F_) return;
    int f  = idx & (F_ - 1);
    int id = ids[idx];
    const float4* src = reinterpret_cast<const float4*>(emb + ((size_t)f * V_ + id) * DE);
    float4 v0 = src[0], v1 = src[1], v2 = src[2], v3 = src[3];

    __align__(16) f16 hv[16];
    float vals[16] = {v0.x,v0.y,v0.z,v0.w, v1.x,v1.y,v1.z,v1.w,
                      v2.x,v2.y,v2.z,v2.w, v3.x,v3.y,v3.z,v3.w};
    #pragma unroll
    for (int j = 0; j < 16; j++) hv[j] = __float2half_rn(vals[j]);
    uint4* dh = reinterpret_cast<uint4*>(g_Xf + (size_t)idx * DE);
    dh[0] = ((uint4*)hv)[0]; dh[1] = ((uint4*)hv)[1];
}

// ---------------- weight transpose -> fp16: W[E,K,N] -> T[E,N,K] ----------------
__global__ void wconv_kernel(const float* __restrict__ W, f16* __restrict__ T_,
                             int K, int N) {
    __shared__ float t[32][33];
    int e = blockIdx.z, n0 = blockIdx.x * 32, k0 = blockIdx.y * 32;
    int tx = threadIdx.x, ty = threadIdx.y;
    #pragma unroll
    for (int j = 0; j < 4; j++)
        t[ty + 8 * j][tx] = W[((size_t)e * K + k0 + ty + 8 * j) * N + n0 + tx];
    __syncthreads();
    #pragma unroll
    for (int j = 0; j < 4; j++) {
        int n = n0 + ty + 8 * j, k = k0 + tx;
        T_[((size_t)e * N + n) * K + k] = __float2half_rn(t[tx][ty + 8 * j]);
    }
}

// ---------------- warp helpers ----------------
__device__ __forceinline__ float warp_allreduce(float v) {
    #pragma unroll
    for (int o = 16; o > 0; o >>= 1) v += __shfl_xor_sync(0xffffffffu, v, o);
    return v;
}

// ---------------- level-1 gates + combine ----------------
__global__ void gate1_kernel(const float* __restrict__ Wst, const float* __restrict__ bst,
                             const float* __restrict__ Wsh, const float* __restrict__ bsh)
{
    int warp = threadIdx.x >> 5, lane = threadIdx.x & 31;
    int b = blockIdx.x * 8 + warp;

    const f16* x = g_Xf + (size_t)b * DIN;
    float xr[16];
    #pragma unroll
    for (int j = 0; j < 16; j++) xr[j] = __half2float(x[lane + 32 * j]);

    float logit[14];
    #pragma unroll
    for (int L = 0; L < 14; L++) {
        float acc = 0.f;
        if (L < 8) {
            int t = L >> 2, k = L & 3;
            const float* wc = Wst + (size_t)t * DIN * 4 + k;
            #pragma unroll
            for (int j = 0; j < 16; j++) acc += xr[j] * wc[(lane + 32 * j) * 4];
        } else {
            const float* wc = Wsh + (L - 8);
            #pragma unroll
            for (int j = 0; j < 16; j++) acc += xr[j] * wc[(lane + 32 * j) * 6];
        }
        acc = warp_allreduce(acc);
        logit[L] = acc + ((L < 8) ? bst[(L >> 2) * 4 + (L & 3)] : bsh[L - 8]);
    }

    float g0[4], g1[4], gs[6];
    {
        float m = fmaxf(fmaxf(logit[0], logit[1]), fmaxf(logit[2], logit[3]));
        float s = 0.f;
        #pragma unroll
        for (int k = 0; k < 4; k++) { g0[k] = expf(logit[k] - m); s += g0[k]; }
        #pragma unroll
        for (int k = 0; k < 4; k++) g0[k] /= s;
    }
    {
        float m = fmaxf(fmaxf(logit[4], logit[5]), fmaxf(logit[6], logit[7]));
        float s = 0.f;
        #pragma unroll
        for (int k = 0; k < 4; k++) { g1[k] = expf(logit[4 + k] - m); s += g1[k]; }
        #pragma unroll
        for (int k = 0; k < 4; k++) g1[k] /= s;
    }
    {
        float m = logit[8];
        #pragma unroll
        for (int k = 9; k < 14; k++) m = fmaxf(m, logit[k]);
        float s = 0.f;
        #pragma unroll
        for (int k = 0; k < 6; k++) { gs[k] = expf(logit[8 + k] - m); s += gs[k]; }
        #pragma unroll
        for (int k = 0; k < 6; k++) gs[k] /= s;
    }

    #pragma unroll
    for (int it = 0; it < 8; it++) {
        int c = lane + 32 * it;
        float v[6];
        #pragma unroll
        for (int e = 0; e < 6; e++) v[e] = __half2float(g_O[((size_t)e * B_ + b) * H2_ + c]);
        float o0 = g0[0]*v[0] + g0[1]*v[1] + g0[2]*v[4] + g0[3]*v[5];
        float o1 = g1[0]*v[2] + g1[1]*v[3] + g1[2]*v[4] + g1[3]*v[5];
        float os = 0.f;
        #pragma unroll
        for (int e = 0; e < 6; e++) os += gs[e] * v[e];
        g_X2f[((size_t)0 * B_ + b) * H2_ + c] = __float2half_rn(o0);
        g_X2f[((size_t)1 * B_ + b) * H2_ + c] = __float2half_rn(o1);
        g_X2f[((size_t)2 * B_ + b) * H2_ + c] = __float2half_rn(os);
    }
}

// ---------------- level-2 gates + combine ----------------
__global__ void gate2_kernel(const float* __restrict__ Wst, const float* __restrict__ bst)
{
    int warp = threadIdx.x >> 5, lane = threadIdx.x & 31;
    int b = blockIdx.x * 8 + warp;

    float x0r[8], x1r[8];
    const f16* x0 = g_X2f + ((size_t)0 * B_ + b) * H2_;
    const f16* x1 = g_X2f + ((size_t)1 * B_ + b) * H2_;
    #pragma unroll
    for (int j = 0; j < 8; j++) {
        x0r[j] = __half2float(x0[lane + 32*j]);
        x1r[j] = __half2float(x1[lane + 32*j]);
    }

    float logit[8];
    #pragma unroll
    for (int L = 0; L < 8; L++) {
        int t = L >> 2, k = L & 3;
        const float* wc = Wst + (size_t)t * H2_ * 4 + k;
        float acc = 0.f;
        if (t == 0) {
            #pragma unroll
            for (int j = 0; j < 8; j++) acc += x0r[j] * wc[(lane + 32*j) * 4];
        } else {
            #pragma unroll
            for (int j = 0; j < 8; j++) acc += x1r[j] * wc[(lane + 32*j) * 4];
        }
        acc = warp_allreduce(acc);
        logit[L] = acc + bst[t * 4 + k];
    }

    float g0[4], g1[4];
    {
        float m = fmaxf(fmaxf(logit[0], logit[1]), fmaxf(logit[2], logit[3]));
        float s = 0.f;
        #pragma unroll
        for (int k = 0; k < 4; k++) { g0[k] = expf(logit[k] - m); s += g0[k]; }
        #pragma unroll
        for (int k = 0; k < 4; k++) g0[k] /= s;
    }
    {
        float m = fmaxf(fmaxf(logit[4], logit[5]), fmaxf(logit[6], logit[7]));
        float s = 0.f;
        #pragma unroll
        for (int k = 0; k < 4; k++) { g1[k] = expf(logit[4 + k] - m); s += g1[k]; }
        #pragma unroll
        for (int k = 0; k < 4; k++) g1[k] /= s;
    }

    #pragma unroll
    for (int it = 0; it < 8; it++) {
        int c = lane + 32 * it;
        float v[6];
        #pragma unroll
        for (int e = 0; e < 6; e++) v[e] = __half2float(g_O[((size_t)e * B_ + b) * H2_ + c]);
        float o0 = g0[0]*v[0] + g0[1]*v[1] + g0[2]*v[4] + g0[3]*v[5];
        float o1 = g1[0]*v[2] + g1[1]*v[3] + g1[2]*v[4] + g1[3]*v[5];
        g_X3f[((size_t)0 * B_ + b) * H2_ + c] = __float2half_rn(o0);
        g_X3f[((size_t)1 * B_ + b) * H2_ + c] = __float2half_rn(o1);
    }
}

// ---------------- launcher ----------------
extern "C" void kernel_launch(void* const* d_in, const int* in_sizes, int n_in,
                              void* d_out, int out_size) {
    const int*   x_ids = (const int*)  d_in[0];
    const float* emb   = (const float*)d_in[1];
    const float* e1_W1 = (const float*)d_in[2];
    const float* e1_b1 = (const float*)d_in[3];
    const float* e1_W2 = (const float*)d_in[4];
    const float* e1_b2 = (const float*)d_in[5];
    const float* g1_Ws = (const float*)d_in[6];
    const float* g1_bs = (const float*)d_in[7];
    const float* g1_Wsh= (const float*)d_in[8];
    const float* g1_bsh= (const float*)d_in[9];
    const float* e2_W1 = (const float*)d_in[10];
    const float* e2_b1 = (const float*)d_in[11];
    const float* e2_W2 = (const float*)d_in[12];
    const float* e2_b2 = (const float*)d_in[13];
    const float* g2_Ws = (const float*)d_in[14];
    const float* g2_bs = (const float*)d_in[15];
    const float* tw_W1 = (const float*)d_in[16];
    const float* tw_b1 = (const float*)d_in[17];
    const float* tw_W2 = (const float*)d_in[18];
    const float* tw_b2 = (const float*)d_in[19];

    f16 *pXf,*pHf,*pO,*pX2f,*pX3f,*pTf;
    f16 *w1,*w2,*w3,*w4,*w5,*w6;
    cudaGetSymbolAddress((void**)&pXf,  g_Xf);
    cudaGetSymbolAddress((void**)&pHf,  g_Hf);
    cudaGetSymbolAddress((void**)&pO,   g_O);
    cudaGetSymbolAddress((void**)&pX2f, g_X2f);
    cudaGetSymbolAddress((void**)&pX3f, g_X3f);
    cudaGetSymbolAddress((void**)&pTf,  g_Tf);
    cudaGetSymbolAddress((void**)&w1, g_w1);
    cudaGetSymbolAddress((void**)&w2, g_w2);
    cudaGetSymbolAddress((void**)&w3, g_w3);
    cudaGetSymbolAddress((void**)&w4, g_w4);
    cudaGetSymbolAddress((void**)&w5, g_w5);
    cudaGetSymbolAddress((void**)&w6, g_w6);

    const int SM128 = 2 * (128 * 128 + 128 * 128);   // 65536
    const int SM64  = 2 * (128 * 128 + 64 * 128);    // 49152
    cudaFuncSetAttribute((const void*)gemm_mma<128,0,1>, cudaFuncAttributeMaxDynamicSharedMemorySize, SM128);
    cudaFuncSetAttribute((const void*)gemm_mma<64,1,0>,  cudaFuncAttributeMaxDynamicSharedMemorySize, SM64);

    dim3 tb(32, 8);
    // weight prep (transpose + fp16 convert)
    wconv_kernel<<<dim3(H1_/32, DIN/32, NE), tb>>>(e1_W1, w1, DIN, H1_);
    wconv_kernel<<<dim3(H2_/32, H1_/32, NE), tb>>>(e1_W2, w2, H1_, H2_);
    wconv_kernel<<<dim3(H1_/32, H2_/32, NE), tb>>>(e2_W1, w3, H2_, H1_);
    wconv_kernel<<<dim3(H2_/32, H1_/32, NE), tb>>>(e2_W2, w4, H1_, H2_);
    wconv_kernel<<<dim3(T1_/32, H2_/32, 2),  tb>>>(tw_W1, w5, H2_, T1_);
    wconv_kernel<<<dim3(T2_/32, T1_/32, 2),  tb>>>(tw_W2, w6, T1_, T2_);

    // embedding gather -> fp16
    gather_kernel<<<(B_ * F_) / 256, 256>>>(x_ids, emb);

    // L1 experts stage 1: relu(X @ W1) -> H fp16   (shared A)
    gemm_mma<128,0,1><<<dim3(H1_/128, B_/128, NE), 256, SM128>>>(
        pXf, w1, e1_b1, nullptr, pHf,
        DIN, H1_, 0, 0, (size_t)B_*H1_, H1_);
    // L1 experts stage 2: relu(H @ W2) -> O fp16
    gemm_mma<128,0,1><<<dim3(H2_/128, B_/128, NE), 256, SM128>>>(
        pHf, w2, e1_b2, nullptr, pO,
        H1_, H2_, 2, (size_t)B_*H1_, (size_t)B_*H2_, H2_);
    // L1 gates + combine -> X2 fp16
    gate1_kernel<<<B_/8, 256>>>(g1_Ws, g1_bs, g1_Wsh, g1_bsh);

    // L2 experts stage 1: relu(X2[e/2] @ W1) -> H fp16
    gemm_mma<128,0,1><<<dim3(H1_/128, B_/128, NE), 256, SM128>>>(
        pX2f, w3, e2_b1, nullptr, pHf,
        H2_, H1_, 1, (size_t)B_*H2_, (size_t)B_*H1_, H1_);
    // L2 experts stage 2: relu(H @ W2) -> O fp16
    gemm_mma<128,0,1><<<dim3(H2_/128, B_/128, NE), 256, SM128>>>(
        pHf, w4, e2_b2, nullptr, pO,
        H1_, H2_, 2, (size_t)B_*H1_, (size_t)B_*H2_, H2_);
    // L2 gates + combine -> X3 fp16
    gate2_kernel<<<B_/8, 256>>>(g2_Ws, g2_bs);

    // tower stage 1: relu(X3[t] @ tw_W1) -> T fp16
    gemm_mma<128,0,1><<<dim3(T1_/128, B_/128, 2), 256, SM128>>>(
        pX3f, w5, tw_b1, nullptr, pTf,
        H2_, T1_, 2, (size_t)B_*H2_, (size_t)B_*T1_, T1_);
    // tower stage 2: sigmoid(T @ tw_W2) -> d_out [B, 2*64]
    gemm_mma<64,1,0><<<dim3(T2_/64, B_/128, 2), 256, SM64>>>(
        pTf, w6, tw_b2, (float*)d_out, nullptr,
        T1_, T2_, 2, (size_t)B_*T1_, (size_t)T2_, 2*T2_);
}

// round 7
// speedup vs baseline: 6.6133x; 1.2514x over previous
#include <cuda_runtime.h>
#include <cuda_fp16.h>
#include <math.h>
#include <stdint.h>

typedef __half f16;

#define B_   16384
#define F_   32
#define V_   50000
#define DE   16
#define DIN  512
#define NE   6
#define H1_  512
#define H2_  256
#define T1_  128
#define T2_  64

// ---------------- scratch (device globals; no runtime alloc) ----------------
__device__ __align__(256) f16 g_Xf [(size_t)B_*DIN];
__device__ __align__(256) f16 g_Hf [(size_t)NE*B_*H1_];
__device__ __align__(256) f16 g_O  [(size_t)NE*B_*H2_];
__device__ __align__(256) f16 g_X2f[(size_t)3*B_*H2_];
__device__ __align__(256) f16 g_X3f[(size_t)2*B_*H2_];
__device__ __align__(256) f16 g_Tf [(size_t)2*B_*T1_];
__device__ __align__(256) float g_L1[(size_t)B_*64];      // level-1 gate logits (padded 64)
__device__ __align__(256) float g_L2[(size_t)2*B_*64];    // level-2 gate logits
// transposed fp16 weights, layout [E, N, K] (K-major rows)
__device__ __align__(256) f16 g_w1[(size_t)NE*H1_*DIN];
__device__ __align__(256) f16 g_w2[(size_t)NE*H2_*H1_];
__device__ __align__(256) f16 g_w3[(size_t)NE*H1_*H2_];
__device__ __align__(256) f16 g_w4[(size_t)NE*H2_*H1_];
__device__ __align__(256) f16 g_w5[(size_t)2*T1_*H2_];
__device__ __align__(256) f16 g_w6[(size_t)2*T2_*T1_];
// packed gate weights (padded to N=64) + biases
__device__ __align__(256) f16   g_wg1[(size_t)64*DIN];      // rows 0-7 task logits, 8-13 shared, rest 0
__device__ __align__(256) f16   g_wg2[(size_t)2*64*H2_];
__device__ __align__(256) float g_b1p[64];
__device__ __align__(256) float g_b2p[128];

// ---------------- helpers ----------------
__device__ __forceinline__ uint32_t smem_u32(const void* p) {
    uint32_t a;
    asm("{ .reg .u64 t; cvta.to.shared.u64 t, %1; cvt.u32.u64 %0, t; }" : "=r"(a) : "l"(p));
    return a;
}
__device__ __forceinline__ void cp16(uint32_t dst, const void* src) {
    asm volatile("cp.async.cg.shared.global [%0], [%1], 16;" :: "r"(dst), "l"(src));
}
__device__ __forceinline__ void ldsm4(uint32_t* r, uint32_t a) {
    asm volatile("ldmatrix.sync.aligned.m8n8.x4.shared.b16 {%0,%1,%2,%3}, [%4];"
                 : "=r"(r[0]), "=r"(r[1]), "=r"(r[2]), "=r"(r[3]) : "r"(a));
}
__device__ __forceinline__ void mma16816(float* c, const uint32_t* a, const uint32_t* b) {
    asm volatile("mma.sync.aligned.m16n8k16.row.col.f32.f16.f16.f32 "
                 "{%0,%1,%2,%3}, {%4,%5,%6,%7}, {%8,%9}, {%0,%1,%2,%3};"
                 : "+f"(c[0]), "+f"(c[1]), "+f"(c[2]), "+f"(c[3])
                 : "r"(a[0]), "r"(a[1]), "r"(a[2]), "r"(a[3]), "r"(b[0]), "r"(b[1]));
}
__device__ __forceinline__ uint32_t swz(uint32_t off) { return off ^ ((off >> 3) & 0x70); }

// ---------------- fp16 grouped GEMM ----------------
// C[e] = act(A[aidx] @ B[e]^T + bias[e])
// NT: CTA N-tile (128/64). ACT: 0=relu 1=sigmoid 2=none. OUTM: 0=f32, 1=f16.
template<int NT, int ACT, int OUTM>
__global__ void __launch_bounds__(256, 2)
gemm_mma(const f16* __restrict__ A, const f16* __restrict__ B,
         const float* __restrict__ bias,
         float* __restrict__ Cf, f16* __restrict__ Ch,
         int K, int Ntot, int a_sel, size_t aStride, size_t cStride, int ldc)
{
    extern __shared__ char smem_raw[];
    constexpr int ASTG  = 128 * 128;
    constexpr int BSTG  = NT * 128;
    constexpr int STAGE = ASTG + BSTG;
    constexpr int NJ    = NT / 32;

    const int tid  = threadIdx.x;
    const int wid  = tid >> 5;
    const int lane = tid & 31;
    const int e  = blockIdx.z;
    const int m0 = blockIdx.y * 128;
    const int n0 = blockIdx.x * NT;

    const int aidx = (a_sel == 0) ? 0 : ((a_sel == 1) ? (e >> 1) : e);
    const f16* pA = A + (size_t)aidx * aStride + (size_t)m0 * K;
    const f16* pB = B + ((size_t)e * Ntot + n0) * K;

    const uint32_t sb = smem_u32(smem_raw);

    const int wm = wid >> 2, wn = wid & 3;
    const int mw = wm * 64;
    const int nw = wn * (NT / 4);

    float acc[4][NJ][4];
    #pragma unroll
    for (int i = 0; i < 4; i++)
        #pragma unroll
        for (int j = 0; j < NJ; j++)
            #pragma unroll
            for (int q = 0; q < 4; q++) acc[i][j][q] = 0.f;

    auto load_stage = [&](int kt, int st) {
        const uint32_t base = sb + st * STAGE;
        const int k0 = kt * 64;
        #pragma unroll
        for (int t = 0; t < 4; t++) {
            int id = tid + t * 256;
            int r = id >> 3, q = id & 7;
            uint32_t off = swz((uint32_t)(r * 128 + q * 16));
            cp16(base + off, pA + (size_t)r * K + k0 + q * 8);
        }
        #pragma unroll
        for (int t = 0; t < NT / 32; t++) {
            int id = tid + t * 256;
            int r = id >> 3, q = id & 7;
            uint32_t off = swz((uint32_t)(r * 128 + q * 16));
            cp16(base + ASTG + off, pB + (size_t)r * K + k0 + q * 8);
        }
        asm volatile("cp.async.commit_group;" ::: "memory");
    };

    load_stage(0, 0);
    const int T = K >> 6;
    for (int kt = 0; kt < T; kt++) {
        if (kt + 1 < T) {
            load_stage(kt + 1, (kt + 1) & 1);
            asm volatile("cp.async.wait_group 1;" ::: "memory");
        } else {
            asm volatile("cp.async.wait_group 0;" ::: "memory");
        }
        __syncthreads();

        const uint32_t abase = sb + (kt & 1) * STAGE;
        const uint32_t bbase = abase + ASTG;

        #pragma unroll
        for (int ks = 0; ks < 4; ks++) {
            const int cb = ks * 32 + (lane >> 4) * 16;
            uint32_t af[4][4];
            #pragma unroll
            for (int i = 0; i < 4; i++) {
                int row = mw + i * 16 + (lane & 15);
                ldsm4(af[i], abase + swz((uint32_t)(row * 128 + cb)));
            }
            uint32_t bf[NJ][2];
            #pragma unroll
            for (int bb = 0; bb < NT / 64; bb++) {
                int row = nw + bb * 16 + (lane & 15);
                uint32_t tr[4];
                ldsm4(tr, bbase + swz((uint32_t)(row * 128 + cb)));
                bf[2*bb][0] = tr[0]; bf[2*bb+1][0] = tr[1];
                bf[2*bb][1] = tr[2]; bf[2*bb+1][1] = tr[3];
            }
            #pragma unroll
            for (int i = 0; i < 4; i++)
                #pragma unroll
                for (int j = 0; j < NJ; j++)
                    mma16816(acc[i][j], af[i], bf[j]);
        }
        __syncthreads();
    }

    // epilogue
    const int lr  = lane >> 2;
    const int lc2 = (lane & 3) * 2;
    #pragma unroll
    for (int i = 0; i < 4; i++)
        #pragma unroll
        for (int j = 0; j < NJ; j++) {
            int col = n0 + nw + j * 8 + lc2;
            float b0 = __ldg(bias + (size_t)e * Ntot + col);
            float b1 = __ldg(bias + (size_t)e * Ntot + col + 1);
            #pragma unroll
            for (int h = 0; h < 2; h++) {
                int row = m0 + mw + i * 16 + lr + h * 8;
                float v0 = acc[i][j][2 * h + 0] + b0;
                float v1 = acc[i][j][2 * h + 1] + b1;
                if (ACT == 0) { v0 = fmaxf(v0, 0.f); v1 = fmaxf(v1, 0.f); }
                else if (ACT == 1) { v0 = 1.f / (1.f + __expf(-v0)); v1 = 1.f / (1.f + __expf(-v1)); }
                size_t gi = (size_t)e * cStride + (size_t)row * ldc + col;
                if (OUTM == 0) {
                    *reinterpret_cast<float2*>(Cf + gi) = make_float2(v0, v1);
                } else {
                    *reinterpret_cast<__half2*>(Ch + gi) = __floats2half2_rn(v0, v1);
                }
            }
        }
}

// ---------------- embedding gather -> fp16 ----------------
__global__ void gather_kernel(const int* __restrict__ ids, const float* __restrict__ emb) {
    int idx = blockIdx.x * blockDim.x + threadIdx.x;
    if (idx >= B_ * F_) return;
    int f  = idx & (F_ - 1);
    int id = ids[idx];
    const float4* src = reinterpret_cast<const float4*>(emb + ((size_t)f * V_ + id) * DE);
    float4 v0 = src[0], v1 = src[1], v2 = src[2], v3 = src[3];
    __align__(16) f16 hv[16];
    float vals[16] = {v0.x,v0.y,v0.z,v0.w, v1.x,v1.y,v1.z,v1.w,
                      v2.x,v2.y,v2.z,v2.w, v3.x,v3.y,v3.z,v3.w};
    #pragma unroll
    for (int j = 0; j < 16; j++) hv[j] = __float2half_rn(vals[j]);
    uint4* dh = reinterpret_cast<uint4*>(g_Xf + (size_t)idx * DE);
    dh[0] = ((uint4*)hv)[0]; dh[1] = ((uint4*)hv)[1];
}

// ---------------- merged weight transpose -> fp16 (all six weights) ----------------
// segment table (compile-time): tiles = E * (K/32) * (N/32)
__global__ void wconv_all(const float* __restrict__ s1, const float* __restrict__ s2,
                          const float* __restrict__ s3, const float* __restrict__ s4,
                          const float* __restrict__ s5, const float* __restrict__ s6)
{
    __shared__ float t[32][33];
    int b = blockIdx.x;
    const float* src; f16* dst; int K, N, loc;
    if (b < 1536)      { src = s1; dst = g_w1; K = DIN; N = H1_; loc = b; }
    else if (b < 2304) { src = s2; dst = g_w2; K = H1_; N = H2_; loc = b - 1536; }
    else if (b < 3072) { src = s3; dst = g_w3; K = H2_; N = H1_; loc = b - 2304; }
    else if (b < 3840) { src = s4; dst = g_w4; K = H1_; N = H2_; loc = b - 3072; }
    else if (b < 3904) { src = s5; dst = g_w5; K = H2_; N = T1_; loc = b - 3840; }
    else               { src = s6; dst = g_w6; K = T1_; N = T2_; loc = b - 3904; }
    int tX = N >> 5, tY = K >> 5;
    int e  = loc / (tX * tY);
    int r  = loc % (tX * tY);
    int k0 = (r / tX) * 32, n0 = (r % tX) * 32;
    int tx = threadIdx.x, ty = threadIdx.y;
    #pragma unroll
    for (int j = 0; j < 4; j++)
        t[ty + 8 * j][tx] = src[((size_t)e * K + k0 + ty + 8 * j) * N + n0 + tx];
    __syncthreads();
    #pragma unroll
    for (int j = 0; j < 4; j++) {
        int n = n0 + ty + 8 * j, k = k0 + tx;
        dst[((size_t)e * N + n) * K + k] = __float2half_rn(t[tx][ty + 8 * j]);
    }
}

// ---------------- pack gate weights to [N=64, K] fp16 + padded biases ----------------
__global__ void gpack_kernel(const float* __restrict__ Wst1, const float* __restrict__ bst1,
                             const float* __restrict__ Wsh1, const float* __restrict__ bsh1,
                             const float* __restrict__ Wst2, const float* __restrict__ bst2)
{
    int idx = blockIdx.x * blockDim.x + threadIdx.x;
    if (idx < 64 * DIN) {                                 // wg1
        int r = idx / DIN, d = idx % DIN;
        float v = 0.f;
        if (r < 8)       v = Wst1[(size_t)(r >> 2) * DIN * 4 + d * 4 + (r & 3)];
        else if (r < 14) v = Wsh1[(size_t)d * 6 + (r - 8)];
        g_wg1[(size_t)r * DIN + d] = __float2half_rn(v);
    } else if (idx < 64 * DIN + 2 * 64 * H2_) {           // wg2
        int q = idx - 64 * DIN;
        int tsk = q / (64 * H2_);
        int rr  = q % (64 * H2_);
        int r = rr / H2_, d = rr % H2_;
        float v = (r < 4) ? Wst2[(size_t)tsk * H2_ * 4 + d * 4 + r] : 0.f;
        g_wg2[((size_t)tsk * 64 + r) * H2_ + d] = __float2half_rn(v);
    } else if (idx < 64 * DIN + 2 * 64 * H2_ + 64) {      // b1p
        int i = idx - (64 * DIN + 2 * 64 * H2_);
        g_b1p[i] = (i < 8) ? bst1[i] : ((i < 14) ? bsh1[i - 8] : 0.f);
    } else if (idx < 64 * DIN + 2 * 64 * H2_ + 64 + 128) { // b2p
        int i = idx - (64 * DIN + 2 * 64 * H2_ + 64);
        int tsk = i >> 6, k = i & 63;
        g_b2p[i] = (k < 4) ? bst2[tsk * 4 + k] : 0.f;
    }
}

// ---------------- level-1 combine (logits precomputed) ----------------
__global__ void comb1_kernel() {
    int warp = threadIdx.x >> 5, lane = threadIdx.x & 31;
    int b = blockIdx.x * 8 + warp;

    float lg[14];
    #pragma unroll
    for (int i = 0; i < 14; i++) lg[i] = __ldg(g_L1 + (size_t)b * 64 + i);

    float g0[4], g1[4], gs[6];
    {
        float m = fmaxf(fmaxf(lg[0], lg[1]), fmaxf(lg[2], lg[3]));
        float s = 0.f;
        #pragma unroll
        for (int k = 0; k < 4; k++) { g0[k] = __expf(lg[k] - m); s += g0[k]; }
        #pragma unroll
        for (int k = 0; k < 4; k++) g0[k] /= s;
    }
    {
        float m = fmaxf(fmaxf(lg[4], lg[5]), fmaxf(lg[6], lg[7]));
        float s = 0.f;
        #pragma unroll
        for (int k = 0; k < 4; k++) { g1[k] = __expf(lg[4 + k] - m); s += g1[k]; }
        #pragma unroll
        for (int k = 0; k < 4; k++) g1[k] /= s;
    }
    {
        float m = lg[8];
        #pragma unroll
        for (int k = 9; k < 14; k++) m = fmaxf(m, lg[k]);
        float s = 0.f;
        #pragma unroll
        for (int k = 0; k < 6; k++) { gs[k] = __expf(lg[8 + k] - m); s += gs[k]; }
        #pragma unroll
        for (int k = 0; k < 6; k++) gs[k] /= s;
    }

    #pragma unroll
    for (int it = 0; it < 8; it++) {
        int c = lane + 32 * it;
        float v[6];
        #pragma unroll
        for (int e = 0; e < 6; e++) v[e] = __half2float(g_O[((size_t)e * B_ + b) * H2_ + c]);
        float o0 = g0[0]*v[0] + g0[1]*v[1] + g0[2]*v[4] + g0[3]*v[5];
        float o1 = g1[0]*v[2] + g1[1]*v[3] + g1[2]*v[4] + g1[3]*v[5];
        float os = 0.f;
        #pragma unroll
        for (int e = 0; e < 6; e++) os += gs[e] * v[e];
        g_X2f[((size_t)0 * B_ + b) * H2_ + c] = __float2half_rn(o0);
        g_X2f[((size_t)1 * B_ + b) * H2_ + c] = __float2half_rn(o1);
        g_X2f[((size_t)2 * B_ + b) * H2_ + c] = __float2half_rn(os);
    }
}

// ---------------- level-2 combine ----------------
__global__ void comb2_kernel() {
    int warp = threadIdx.x >> 5, lane = threadIdx.x & 31;
    int b = blockIdx.x * 8 + warp;

    float l0[4], l1[4];
    #pragma unroll
    for (int k = 0; k < 4; k++) {
        l0[k] = __ldg(g_L2 + ((size_t)0 * B_ + b) * 64 + k);
        l1[k] = __ldg(g_L2 + ((size_t)1 * B_ + b) * 64 + k);
    }

    float g0[4], g1[4];
    {
        float m = fmaxf(fmaxf(l0[0], l0[1]), fmaxf(l0[2], l0[3]));
        float s = 0.f;
        #pragma unroll
        for (int k = 0; k < 4; k++) { g0[k] = __expf(l0[k] - m); s += g0[k]; }
        #pragma unroll
        for (int k = 0; k < 4; k++) g0[k] /= s;
    }
    {
        float m = fmaxf(fmaxf(l1[0], l1[1]), fmaxf(l1[2], l1[3]));
        float s = 0.f;
        #pragma unroll
        for (int k = 0; k < 4; k++) { g1[k] = __expf(l1[k] - m); s += g1[k]; }
        #pragma unroll
        for (int k = 0; k < 4; k++) g1[k] /= s;
    }

    #pragma unroll
    for (int it = 0; it < 8; it++) {
        int c = lane + 32 * it;
        float v[6];
        #pragma unroll
        for (int e = 0; e < 6; e++) v[e] = __half2float(g_O[((size_t)e * B_ + b) * H2_ + c]);
        float o0 = g0[0]*v[0] + g0[1]*v[1] + g0[2]*v[4] + g0[3]*v[5];
        float o1 = g1[0]*v[2] + g1[1]*v[3] + g1[2]*v[4] + g1[3]*v[5];
        g_X3f[((size_t)0 * B_ + b) * H2_ + c] = __float2half_rn(o0);
        g_X3f[((size_t)1 * B_ + b) * H2_ + c] = __float2half_rn(o1);
    }
}

// ---------------- launcher ----------------
extern "C" void kernel_launch(void* const* d_in, const int* in_sizes, int n_in,
                              void* d_out, int out_size) {
    const int*   x_ids = (const int*)  d_in[0];
    const float* emb   = (const float*)d_in[1];
    const float* e1_W1 = (const float*)d_in[2];
    const float* e1_b1 = (const float*)d_in[3];
    const float* e1_W2 = (const float*)d_in[4];
    const float* e1_b2 = (const float*)d_in[5];
    const float* g1_Ws = (const float*)d_in[6];
    const float* g1_bs = (const float*)d_in[7];
    const float* g1_Wsh= (const float*)d_in[8];
    const float* g1_bsh= (const float*)d_in[9];
    const float* e2_W1 = (const float*)d_in[10];
    const float* e2_b1 = (const float*)d_in[11];
    const float* e2_W2 = (const float*)d_in[12];
    const float* e2_b2 = (const float*)d_in[13];
    const float* g2_Ws = (const float*)d_in[14];
    const float* g2_bs = (const float*)d_in[15];
    const float* tw_W1 = (const float*)d_in[16];
    const float* tw_b1 = (const float*)d_in[17];
    const float* tw_W2 = (const float*)d_in[18];
    const float* tw_b2 = (const float*)d_in[19];

    f16 *pXf,*pHf,*pO,*pX2f,*pX3f,*pTf,*w1,*w2,*w3,*w4,*w5,*w6,*wg1,*wg2;
    float *pL1,*pL2,*b1p,*b2p;
    cudaGetSymbolAddress((void**)&pXf,  g_Xf);
    cudaGetSymbolAddress((void**)&pHf,  g_Hf);
    cudaGetSymbolAddress((void**)&pO,   g_O);
    cudaGetSymbolAddress((void**)&pX2f, g_X2f);
    cudaGetSymbolAddress((void**)&pX3f, g_X3f);
    cudaGetSymbolAddress((void**)&pTf,  g_Tf);
    cudaGetSymbolAddress((void**)&pL1,  g_L1);
    cudaGetSymbolAddress((void**)&pL2,  g_L2);
    cudaGetSymbolAddress((void**)&w1, g_w1);
    cudaGetSymbolAddress((void**)&w2, g_w2);
    cudaGetSymbolAddress((void**)&w3, g_w3);
    cudaGetSymbolAddress((void**)&w4, g_w4);
    cudaGetSymbolAddress((void**)&w5, g_w5);
    cudaGetSymbolAddress((void**)&w6, g_w6);
    cudaGetSymbolAddress((void**)&wg1, g_wg1);
    cudaGetSymbolAddress((void**)&wg2, g_wg2);
    cudaGetSymbolAddress((void**)&b1p, g_b1p);
    cudaGetSymbolAddress((void**)&b2p, g_b2p);

    const int SM128 = 2 * (128 * 128 + 128 * 128);   // 65536
    const int SM64  = 2 * (128 * 128 + 64 * 128);    // 49152
    cudaFuncSetAttribute((const void*)gemm_mma<128,0,1>, cudaFuncAttributeMaxDynamicSharedMemorySize, SM128);
    cudaFuncSetAttribute((const void*)gemm_mma<64,2,0>,  cudaFuncAttributeMaxDynamicSharedMemorySize, SM64);
    cudaFuncSetAttribute((const void*)gemm_mma<64,1,0>,  cudaFuncAttributeMaxDynamicSharedMemorySize, SM64);

    // prep: all weight transposes in one launch + gate weight pack + gather
    wconv_all<<<3920, dim3(32, 8)>>>(e1_W1, e1_W2, e2_W1, e2_W2, tw_W1, tw_W2);
    gpack_kernel<<<(64*DIN + 2*64*H2_ + 64 + 128 + 255) / 256, 256>>>(
        g1_Ws, g1_bs, g1_Wsh, g1_bsh, g2_Ws, g2_bs);
    gather_kernel<<<(B_ * F_) / 256, 256>>>(x_ids, emb);

    // L1 experts
    gemm_mma<128,0,1><<<dim3(H1_/128, B_/128, NE), 256, SM128>>>(
        pXf, w1, e1_b1, nullptr, pHf, DIN, H1_, 0, 0, (size_t)B_*H1_, H1_);
    gemm_mma<128,0,1><<<dim3(H2_/128, B_/128, NE), 256, SM128>>>(
        pHf, w2, e1_b2, nullptr, pO, H1_, H2_, 2, (size_t)B_*H1_, (size_t)B_*H2_, H2_);
    // L1 gate logits (X @ wg1 -> [B,64] f32) + combine
    gemm_mma<64,2,0><<<dim3(1, B_/128, 1), 256, SM64>>>(
        pXf, wg1, b1p, pL1, nullptr, DIN, 64, 0, 0, 0, 64);
    comb1_kernel<<<B_/8, 256>>>();

    // L2 experts
    gemm_mma<128,0,1><<<dim3(H1_/128, B_/128, NE), 256, SM128>>>(
        pX2f, w3, e2_b1, nullptr, pHf, H2_, H1_, 1, (size_t)B_*H2_, (size_t)B_*H1_, H1_);
    gemm_mma<128,0,1><<<dim3(H2_/128, B_/128, NE), 256, SM128>>>(
        pHf, w4, e2_b2, nullptr, pO, H1_, H2_, 2, (size_t)B_*H1_, (size_t)B_*H2_, H2_);
    // L2 gate logits (X2[t] @ wg2[t]) + combine
    gemm_mma<64,2,0><<<dim3(1, B_/128, 2), 256, SM64>>>(
        pX2f, wg2, b2p, pL2, nullptr, H2_, 64, 2, (size_t)B_*H2_, (size_t)B_*64, 64);
    comb2_kernel<<<B_/8, 256>>>();

    // towers
    gemm_mma<128,0,1><<<dim3(T1_/128, B_/128, 2), 256, SM128>>>(
        pX3f, w5, tw_b1, nullptr, pTf, H2_, T1_, 2, (size_t)B_*H2_, (size_t)B_*T1_, T1_);
    gemm_mma<64,1,0><<<dim3(T2_/64, B_/128, 2), 256, SM64>>>(
        pTf, w6, tw_b2, (float*)d_out, nullptr, T1_, T2_, 2, (size_t)B_*T1_, (size_t)T2_, 2*T2_);
}

// round 8
// speedup vs baseline: 6.7850x; 1.0260x over previous
#include <cuda_runtime.h>
#include <cuda_fp16.h>
#include <math.h>
#include <stdint.h>

typedef __half f16;

#define B_   16384
#define F_   32
#define V_   50000
#define DE   16
#define DIN  512
#define NE   6
#define H1_  512
#define H2_  256
#define T1_  128
#define T2_  64

// ---------------- scratch (device globals; no runtime alloc) ----------------
__device__ __align__(256) f16 g_Xf [(size_t)B_*DIN];
__device__ __align__(256) f16 g_Hf [(size_t)NE*B_*H1_];
__device__ __align__(256) f16 g_O  [(size_t)NE*B_*H2_];
__device__ __align__(256) f16 g_X2f[(size_t)3*B_*H2_];
__device__ __align__(256) f16 g_X3f[(size_t)2*B_*H2_];
__device__ __align__(256) f16 g_Tf [(size_t)2*B_*T1_];
__device__ __align__(256) float g_L1[(size_t)B_*64];
__device__ __align__(256) float g_L2[(size_t)2*B_*64];
// transposed fp16 weights, layout [E, N, K] (K-major rows)
__device__ __align__(256) f16 g_w1[(size_t)NE*H1_*DIN];
__device__ __align__(256) f16 g_w2[(size_t)NE*H2_*H1_];
__device__ __align__(256) f16 g_w3[(size_t)NE*H1_*H2_];
__device__ __align__(256) f16 g_w4[(size_t)NE*H2_*H1_];
__device__ __align__(256) f16 g_w5[(size_t)2*T1_*H2_];
__device__ __align__(256) f16 g_w6[(size_t)2*T2_*T1_];
// packed gate weights (padded to N=64) + biases
__device__ __align__(256) f16   g_wg1[(size_t)64*DIN];
__device__ __align__(256) f16   g_wg2[(size_t)2*64*H2_];
__device__ __align__(256) float g_b1p[64];
__device__ __align__(256) float g_b2p[128];

// ---------------- helpers ----------------
__device__ __forceinline__ uint32_t smem_u32(const void* p) {
    uint32_t a;
    asm("{ .reg .u64 t; cvta.to.shared.u64 t, %1; cvt.u32.u64 %0, t; }" : "=r"(a) : "l"(p));
    return a;
}
__device__ __forceinline__ void cp16(uint32_t dst, const void* src) {
    asm volatile("cp.async.cg.shared.global [%0], [%1], 16;" :: "r"(dst), "l"(src));
}
__device__ __forceinline__ void ldsm4(uint32_t* r, uint32_t a) {
    asm volatile("ldmatrix.sync.aligned.m8n8.x4.shared.b16 {%0,%1,%2,%3}, [%4];"
                 : "=r"(r[0]), "=r"(r[1]), "=r"(r[2]), "=r"(r[3]) : "r"(a));
}
__device__ __forceinline__ void mma16816(float* c, const uint32_t* a, const uint32_t* b) {
    asm volatile("mma.sync.aligned.m16n8k16.row.col.f32.f16.f16.f32 "
                 "{%0,%1,%2,%3}, {%4,%5,%6,%7}, {%8,%9}, {%0,%1,%2,%3};"
                 : "+f"(c[0]), "+f"(c[1]), "+f"(c[2]), "+f"(c[3])
                 : "r"(a[0]), "r"(a[1]), "r"(a[2]), "r"(a[3]), "r"(b[0]), "r"(b[1]));
}
__device__ __forceinline__ uint32_t swz(uint32_t off) { return off ^ ((off >> 3) & 0x70); }

// ---------------- fp16 grouped GEMM, 4 warps, 64x(NT/2) warp tiles ----------------
// C[e] = act(A[aidx] @ B[e]^T + bias[e])
// NT: CTA N-tile (128/64). ACT: 0=relu 1=sigmoid 2=none. OUTM: 0=f32, 1=f16.
template<int NT, int ACT, int OUTM>
__global__ void __launch_bounds__(128, 2)
gemm_mma(const f16* __restrict__ A, const f16* __restrict__ B,
         const float* __restrict__ bias,
         float* __restrict__ Cf, f16* __restrict__ Ch,
         int K, int Ntot, int a_sel, size_t aStride, size_t cStride, int ldc)
{
    extern __shared__ char smem_raw[];
    constexpr int ASTG  = 128 * 128;          // 128 rows x 128B (64 f16)
    constexpr int BSTG  = NT * 128;
    constexpr int STAGE = ASTG + BSTG;
    constexpr int WN    = NT / 2;             // warp N tile
    constexpr int NJ    = WN / 8;             // n8 tiles per warp
    constexpr int NB    = WN / 16;            // B ldsm4 per ks

    const int tid  = threadIdx.x;
    const int wid  = tid >> 5;
    const int lane = tid & 31;
    const int e  = blockIdx.z;
    const int m0 = blockIdx.y * 128;
    const int n0 = blockIdx.x * NT;

    const int aidx = (a_sel == 0) ? 0 : ((a_sel == 1) ? (e >> 1) : e);
    const f16* pA = A + (size_t)aidx * aStride + (size_t)m0 * K;
    const f16* pB = B + ((size_t)e * Ntot + n0) * K;

    const uint32_t sb = smem_u32(smem_raw);

    // warp grid 2 x 2; warp tile 64 x WN
    const int wm = wid >> 1, wn = wid & 1;
    const int mw = wm * 64;
    const int nw = wn * WN;

    float acc[4][NJ][4];
    #pragma unroll
    for (int i = 0; i < 4; i++)
        #pragma unroll
        for (int j = 0; j < NJ; j++)
            #pragma unroll
            for (int q = 0; q < 4; q++) acc[i][j][q] = 0.f;

    auto load_stage = [&](int kt, int st) {
        const uint32_t base = sb + st * STAGE;
        const int k0 = kt * 64;
        #pragma unroll
        for (int t = 0; t < 8; t++) {                 // A: 1024 chunks / 128 thr
            int id = tid + t * 128;
            int r = id >> 3, q = id & 7;
            uint32_t off = swz((uint32_t)(r * 128 + q * 16));
            cp16(base + off, pA + (size_t)r * K + k0 + q * 8);
        }
        #pragma unroll
        for (int t = 0; t < NT / 16; t++) {           // B: NT*8 chunks / 128 thr
            int id = tid + t * 128;
            int r = id >> 3, q = id & 7;
            uint32_t off = swz((uint32_t)(r * 128 + q * 16));
            cp16(base + ASTG + off, pB + (size_t)r * K + k0 + q * 8);
        }
        asm volatile("cp.async.commit_group;" ::: "memory");
    };

    load_stage(0, 0);
    const int T = K >> 6;
    for (int kt = 0; kt < T; kt++) {
        if (kt + 1 < T) {
            load_stage(kt + 1, (kt + 1) & 1);
            asm volatile("cp.async.wait_group 1;" ::: "memory");
        } else {
            asm volatile("cp.async.wait_group 0;" ::: "memory");
        }
        __syncthreads();

        const uint32_t abase = sb + (kt & 1) * STAGE;
        const uint32_t bbase = abase + ASTG;

        #pragma unroll
        for (int ks = 0; ks < 4; ks++) {
            const int cb = ks * 32 + (lane >> 4) * 16;
            uint32_t af[4][4];
            #pragma unroll
            for (int i = 0; i < 4; i++) {
                int row = mw + i * 16 + (lane & 15);
                ldsm4(af[i], abase + swz((uint32_t)(row * 128 + cb)));
            }
            uint32_t bf[NJ][2];
            #pragma unroll
            for (int bb = 0; bb < NB; bb++) {
                int row = nw + bb * 16 + (lane & 15);
                uint32_t tr[4];
                ldsm4(tr, bbase + swz((uint32_t)(row * 128 + cb)));
                bf[2*bb][0] = tr[0]; bf[2*bb+1][0] = tr[1];
                bf[2*bb][1] = tr[2]; bf[2*bb+1][1] = tr[3];
            }
            #pragma unroll
            for (int i = 0; i < 4; i++)
                #pragma unroll
                for (int j = 0; j < NJ; j++)
                    mma16816(acc[i][j], af[i], bf[j]);
        }
        __syncthreads();
    }

    // epilogue
    const int lr  = lane >> 2;
    const int lc2 = (lane & 3) * 2;
    #pragma unroll
    for (int i = 0; i < 4; i++)
        #pragma unroll
        for (int j = 0; j < NJ; j++) {
            int col = n0 + nw + j * 8 + lc2;
            float b0 = __ldg(bias + (size_t)e * Ntot + col);
            float b1 = __ldg(bias + (size_t)e * Ntot + col + 1);
            #pragma unroll
            for (int h = 0; h < 2; h++) {
                int row = m0 + mw + i * 16 + lr + h * 8;
                float v0 = acc[i][j][2 * h + 0] + b0;
                float v1 = acc[i][j][2 * h + 1] + b1;
                if (ACT == 0) { v0 = fmaxf(v0, 0.f); v1 = fmaxf(v1, 0.f); }
                else if (ACT == 1) { v0 = 1.f / (1.f + __expf(-v0)); v1 = 1.f / (1.f + __expf(-v1)); }
                size_t gi = (size_t)e * cStride + (size_t)row * ldc + col;
                if (OUTM == 0) {
                    *reinterpret_cast<float2*>(Cf + gi) = make_float2(v0, v1);
                } else {
                    *reinterpret_cast<__half2*>(Ch + gi) = __floats2half2_rn(v0, v1);
                }
            }
        }
}

// ---------------- embedding gather -> fp16 ----------------
__global__ void gather_kernel(const int* __restrict__ ids, const float* __restrict__ emb) {
    int idx = blockIdx.x * blockDim.x + threadIdx.x;
    if (idx >= B_ * F_) return;
    int f  = idx & (F_ - 1);
    int id = ids[idx];
    const float4* src = reinterpret_cast<const float4*>(emb + ((size_t)f * V_ + id) * DE);
    float4 v0 = src[0], v1 = src[1], v2 = src[2], v3 = src[3];
    __align__(16) f16 hv[16];
    float vals[16] = {v0.x,v0.y,v0.z,v0.w, v1.x,v1.y,v1.z,v1.w,
                      v2.x,v2.y,v2.z,v2.w, v3.x,v3.y,v3.z,v3.w};
    #pragma unroll
    for (int j = 0; j < 16; j++) hv[j] = __float2half_rn(vals[j]);
    uint4* dh = reinterpret_cast<uint4*>(g_Xf + (size_t)idx * DE);
    dh[0] = ((uint4*)hv)[0]; dh[1] = ((uint4*)hv)[1];
}

// ---------------- merged weight transpose -> fp16 (all six weights) ----------------
__global__ void wconv_all(const float* __restrict__ s1, const float* __restrict__ s2,
                          const float* __restrict__ s3, const float* __restrict__ s4,
                          const float* __restrict__ s5, const float* __restrict__ s6)
{
    __shared__ float t[32][33];
    int b = blockIdx.x;
    const float* src; f16* dst; int K, N, loc;
    if (b < 1536)      { src = s1; dst = g_w1; K = DIN; N = H1_; loc = b; }
    else if (b < 2304) { src = s2; dst = g_w2; K = H1_; N = H2_; loc = b - 1536; }
    else if (b < 3072) { src = s3; dst = g_w3; K = H2_; N = H1_; loc = b - 2304; }
    else if (b < 3840) { src = s4; dst = g_w4; K = H1_; N = H2_; loc = b - 3072; }
    else if (b < 3904) { src = s5; dst = g_w5; K = H2_; N = T1_; loc = b - 3840; }
    else               { src = s6; dst = g_w6; K = T1_; N = T2_; loc = b - 3904; }
    int tX = N >> 5, tY = K >> 5;
    int e  = loc / (tX * tY);
    int r  = loc % (tX * tY);
    int k0 = (r / tX) * 32, n0 = (r % tX) * 32;
    int tx = threadIdx.x, ty = threadIdx.y;
    #pragma unroll
    for (int j = 0; j < 4; j++)
        t[ty + 8 * j][tx] = src[((size_t)e * K + k0 + ty + 8 * j) * N + n0 + tx];
    __syncthreads();
    #pragma unroll
    for (int j = 0; j < 4; j++) {
        int n = n0 + ty + 8 * j, k = k0 + tx;
        dst[((size_t)e * N + n) * K + k] = __float2half_rn(t[tx][ty + 8 * j]);
    }
}

// ---------------- pack gate weights to [N=64, K] fp16 + padded biases ----------------
__global__ void gpack_kernel(const float* __restrict__ Wst1, const float* __restrict__ bst1,
                             const float* __restrict__ Wsh1, const float* __restrict__ bsh1,
                             const float* __restrict__ Wst2, const float* __restrict__ bst2)
{
    int idx = blockIdx.x * blockDim.x + threadIdx.x;
    if (idx < 64 * DIN) {
        int r = idx / DIN, d = idx % DIN;
        float v = 0.f;
        if (r < 8)       v = Wst1[(size_t)(r >> 2) * DIN * 4 + d * 4 + (r & 3)];
        else if (r < 14) v = Wsh1[(size_t)d * 6 + (r - 8)];
        g_wg1[(size_t)r * DIN + d] = __float2half_rn(v);
    } else if (idx < 64 * DIN + 2 * 64 * H2_) {
        int q = idx - 64 * DIN;
        int tsk = q / (64 * H2_);
        int rr  = q % (64 * H2_);
        int r = rr / H2_, d = rr % H2_;
        float v = (r < 4) ? Wst2[(size_t)tsk * H2_ * 4 + d * 4 + r] : 0.f;
        g_wg2[((size_t)tsk * 64 + r) * H2_ + d] = __float2half_rn(v);
    } else if (idx < 64 * DIN + 2 * 64 * H2_ + 64) {
        int i = idx - (64 * DIN + 2 * 64 * H2_);
        g_b1p[i] = (i < 8) ? bst1[i] : ((i < 14) ? bsh1[i - 8] : 0.f);
    } else if (idx < 64 * DIN + 2 * 64 * H2_ + 64 + 128) {
        int i = idx - (64 * DIN + 2 * 64 * H2_ + 64);
        int tsk = i >> 6, k = i & 63;
        g_b2p[i] = (k < 4) ? bst2[tsk * 4 + k] : 0.f;
    }
}

// ---------------- level-1 combine ----------------
__global__ void comb1_kernel() {
    int warp = threadIdx.x >> 5, lane = threadIdx.x & 31;
    int b = blockIdx.x * 8 + warp;

    float lg[14];
    #pragma unroll
    for (int i = 0; i < 14; i++) lg[i] = __ldg(g_L1 + (size_t)b * 64 + i);

    float g0[4], g1[4], gs[6];
    {
        float m = fmaxf(fmaxf(lg[0], lg[1]), fmaxf(lg[2], lg[3]));
        float s = 0.f;
        #pragma unroll
        for (int k = 0; k < 4; k++) { g0[k] = __expf(lg[k] - m); s += g0[k]; }
        #pragma unroll
        for (int k = 0; k < 4; k++) g0[k] /= s;
    }
    {
        float m = fmaxf(fmaxf(lg[4], lg[5]), fmaxf(lg[6], lg[7]));
        float s = 0.f;
        #pragma unroll
        for (int k = 0; k < 4; k++) { g1[k] = __expf(lg[4 + k] - m); s += g1[k]; }
        #pragma unroll
        for (int k = 0; k < 4; k++) g1[k] /= s;
    }
    {
        float m = lg[8];
        #pragma unroll
        for (int k = 9; k < 14; k++) m = fmaxf(m, lg[k]);
        float s = 0.f;
        #pragma unroll
        for (int k = 0; k < 6; k++) { gs[k] = __expf(lg[8 + k] - m); s += gs[k]; }
        #pragma unroll
        for (int k = 0; k < 6; k++) gs[k] /= s;
    }

    #pragma unroll
    for (int it = 0; it < 8; it++) {
        int c = lane + 32 * it;
        float v[6];
        #pragma unroll
        for (int e = 0; e < 6; e++) v[e] = __half2float(g_O[((size_t)e * B_ + b) * H2_ + c]);
        float o0 = g0[0]*v[0] + g0[1]*v[1] + g0[2]*v[4] + g0[3]*v[5];
        float o1 = g1[0]*v[2] + g1[1]*v[3] + g1[2]*v[4] + g1[3]*v[5];
        float os = 0.f;
        #pragma unroll
        for (int e = 0; e < 6; e++) os += gs[e] * v[e];
        g_X2f[((size_t)0 * B_ + b) * H2_ + c] = __float2half_rn(o0);
        g_X2f[((size_t)1 * B_ + b) * H2_ + c] = __float2half_rn(o1);
        g_X2f[((size_t)2 * B_ + b) * H2_ + c] = __float2half_rn(os);
    }
}

// ---------------- level-2 combine ----------------
__global__ void comb2_kernel() {
    int warp = threadIdx.x >> 5, lane = threadIdx.x & 31;
    int b = blockIdx.x * 8 + warp;

    float l0[4], l1[4];
    #pragma unroll
    for (int k = 0; k < 4; k++) {
        l0[k] = __ldg(g_L2 + ((size_t)0 * B_ + b) * 64 + k);
        l1[k] = __ldg(g_L2 + ((size_t)1 * B_ + b) * 64 + k);
    }

    float g0[4], g1[4];
    {
        float m = fmaxf(fmaxf(l0[0], l0[1]), fmaxf(l0[2], l0[3]));
        float s = 0.f;
        #pragma unroll
        for (int k = 0; k < 4; k++) { g0[k] = __expf(l0[k] - m); s += g0[k]; }
        #pragma unroll
        for (int k = 0; k < 4; k++) g0[k] /= s;
    }
    {
        float m = fmaxf(fmaxf(l1[0], l1[1]), fmaxf(l1[2], l1[3]));
        float s = 0.f;
        #pragma unroll
        for (int k = 0; k < 4; k++) { g1[k] = __expf(l1[k] - m); s += g1[k]; }
        #pragma unroll
        for (int k = 0; k < 4; k++) g1[k] /= s;
    }

    #pragma unroll
    for (int it = 0; it < 8; it++) {
        int c = lane + 32 * it;
        float v[6];
        #pragma unroll
        for (int e = 0; e < 6; e++) v[e] = __half2float(g_O[((size_t)e * B_ + b) * H2_ + c]);
        float o0 = g0[0]*v[0] + g0[1]*v[1] + g0[2]*v[4] + g0[3]*v[5];
        float o1 = g1[0]*v[2] + g1[1]*v[3] + g1[2]*v[4] + g1[3]*v[5];
        g_X3f[((size_t)0 * B_ + b) * H2_ + c] = __float2half_rn(o0);
        g_X3f[((size_t)1 * B_ + b) * H2_ + c] = __float2half_rn(o1);
    }
}

// ---------------- launcher ----------------
extern "C" void kernel_launch(void* const* d_in, const int* in_sizes, int n_in,
                              void* d_out, int out_size) {
    const int*   x_ids = (const int*)  d_in[0];
    const float* emb   = (const float*)d_in[1];
    const float* e1_W1 = (const float*)d_in[2];
    const float* e1_b1 = (const float*)d_in[3];
    const float* e1_W2 = (const float*)d_in[4];
    const float* e1_b2 = (const float*)d_in[5];
    const float* g1_Ws = (const float*)d_in[6];
    const float* g1_bs = (const float*)d_in[7];
    const float* g1_Wsh= (const float*)d_in[8];
    const float* g1_bsh= (const float*)d_in[9];
    const float* e2_W1 = (const float*)d_in[10];
    const float* e2_b1 = (const float*)d_in[11];
    const float* e2_W2 = (const float*)d_in[12];
    const float* e2_b2 = (const float*)d_in[13];
    const float* g2_Ws = (const float*)d_in[14];
    const float* g2_bs = (const float*)d_in[15];
    const float* tw_W1 = (const float*)d_in[16];
    const float* tw_b1 = (const float*)d_in[17];
    const float* tw_W2 = (const float*)d_in[18];
    const float* tw_b2 = (const float*)d_in[19];

    f16 *pXf,*pHf,*pO,*pX2f,*pX3f,*pTf,*w1,*w2,*w3,*w4,*w5,*w6,*wg1,*wg2;
    float *pL1,*pL2,*b1p,*b2p;
    cudaGetSymbolAddress((void**)&pXf,  g_Xf);
    cudaGetSymbolAddress((void**)&pHf,  g_Hf);
    cudaGetSymbolAddress((void**)&pO,   g_O);
    cudaGetSymbolAddress((void**)&pX2f, g_X2f);
    cudaGetSymbolAddress((void**)&pX3f, g_X3f);
    cudaGetSymbolAddress((void**)&pTf,  g_Tf);
    cudaGetSymbolAddress((void**)&pL1,  g_L1);
    cudaGetSymbolAddress((void**)&pL2,  g_L2);
    cudaGetSymbolAddress((void**)&w1, g_w1);
    cudaGetSymbolAddress((void**)&w2, g_w2);
    cudaGetSymbolAddress((void**)&w3, g_w3);
    cudaGetSymbolAddress((void**)&w4, g_w4);
    cudaGetSymbolAddress((void**)&w5, g_w5);
    cudaGetSymbolAddress((void**)&w6, g_w6);
    cudaGetSymbolAddress((void**)&wg1, g_wg1);
    cudaGetSymbolAddress((void**)&wg2, g_wg2);
    cudaGetSymbolAddress((void**)&b1p, g_b1p);
    cudaGetSymbolAddress((void**)&b2p, g_b2p);

    const int SM128 = 2 * (128 * 128 + 128 * 128);   // 65536
    const int SM64  = 2 * (128 * 128 + 64 * 128);    // 49152
    cudaFuncSetAttribute((const void*)gemm_mma<128,0,1>, cudaFuncAttributeMaxDynamicSharedMemorySize, SM128);
    cudaFuncSetAttribute((const void*)gemm_mma<64,2,0>,  cudaFuncAttributeMaxDynamicSharedMemorySize, SM64);
    cudaFuncSetAttribute((const void*)gemm_mma<64,1,0>,  cudaFuncAttributeMaxDynamicSharedMemorySize, SM64);

    // prep
    wconv_all<<<3920, dim3(32, 8)>>>(e1_W1, e1_W2, e2_W1, e2_W2, tw_W1, tw_W2);
    gpack_kernel<<<(64*DIN + 2*64*H2_ + 64 + 128 + 255) / 256, 256>>>(
        g1_Ws, g1_bs, g1_Wsh, g1_bsh, g2_Ws, g2_bs);
    gather_kernel<<<(B_ * F_) / 256, 256>>>(x_ids, emb);

    // L1 experts
    gemm_mma<128,0,1><<<dim3(H1_/128, B_/128, NE), 128, SM128>>>(
        pXf, w1, e1_b1, nullptr, pHf, DIN, H1_, 0, 0, (size_t)B_*H1_, H1_);
    gemm_mma<128,0,1><<<dim3(H2_/128, B_/128, NE), 128, SM128>>>(
        pHf, w2, e1_b2, nullptr, pO, H1_, H2_, 2, (size_t)B_*H1_, (size_t)B_*H2_, H2_);
    // L1 gate logits + combine
    gemm_mma<64,2,0><<<dim3(1, B_/128, 1), 128, SM64>>>(
        pXf, wg1, b1p, pL1, nullptr, DIN, 64, 0, 0, 0, 64);
    comb1_kernel<<<B_/8, 256>>>();

    // L2 experts
    gemm_mma<128,0,1><<<dim3(H1_/128, B_/128, NE), 128, SM128>>>(
        pX2f, w3, e2_b1, nullptr, pHf, H2_, H1_, 1, (size_t)B_*H2_, (size_t)B_*H1_, H1_);
    gemm_mma<128,0,1><<<dim3(H2_/128, B_/128, NE), 128, SM128>>>(
        pHf, w4, e2_b2, nullptr, pO, H1_, H2_, 2, (size_t)B_*H1_, (size_t)B_*H2_, H2_);
    // L2 gate logits + combine
    gemm_mma<64,2,0><<<dim3(1, B_/128, 2), 128, SM64>>>(
        pX2f, wg2, b2p, pL2, nullptr, H2_, 64, 2, (size_t)B_*H2_, (size_t)B_*64, 64);
    comb2_kernel<<<B_/8, 256>>>();

    // towers
    gemm_mma<128,0,1><<<dim3(T1_/128, B_/128, 2), 128, SM128>>>(
        pX3f, w5, tw_b1, nullptr, pTf, H2_, T1_, 2, (size_t)B_*H2_, (size_t)B_*T1_, T1_);
    gemm_mma<64,1,0><<<dim3(T2_/64, B_/128, 2), 128, SM64>>>(
        pTf, w6, tw_b2, (float*)d_out, nullptr, T1_, T2_, 2, (size_t)B_*T1_, (size_t)T2_, 2*T2_);
}